// round 4
// baseline (speedup 1.0000x reference)
#include <cuda_runtime.h>
#include <math.h>
#include <stdint.h>

#define N_B 8
#define L_S 1024
#define DM  1024
#define H   16
#define D   64
#define QT  16
#define THREADS 512
#define SCALE 0.125f     // 1/sqrt(64)
#define CHUNK 256
#define NCHUNK 4
#define NITER (H * NCHUNK)
#define KTS 257          // kT row stride (odd: conflict-free QK, 2-way PV)
#define BS  20           // e-buffer row stride (mult of 4 for LDS.128)

// SMEM layout (floats)
#define SM_K0  0
#define SM_K1  (D * KTS)                 // 16448
#define SM_B   (2 * D * KTS)             // 32896  e-chunk [256][BS]
#define SM_QS  (SM_B + CHUNK * BS)       // 38016  q tile [D][16]
#define SM_AT  (SM_QS + D * QT)          // 39040  e rows per head [16][1024]
#define SM_TOT (SM_AT + QT * L_S)        // 55424 floats = 221696 B

// packed fp32x2 FMA (2x fp32 throughput on sm_103a, PTX-only)
__device__ __forceinline__ void ffma2(float2& acc, float2 a, float2 b) {
    asm("fma.rn.f32x2 %0, %1, %2, %0;"
        : "+l"(*reinterpret_cast<unsigned long long*>(&acc))
        : "l"(*reinterpret_cast<const unsigned long long*>(&a)),
          "l"(*reinterpret_cast<const unsigned long long*>(&b)));
}

__device__ __forceinline__ void cpa4(uint32_t saddr, const float* g) {
    asm volatile("cp.async.ca.shared.global [%0], [%1], 4;\n"
                 :: "r"(saddr), "l"(g));
}

// Stage chunk c of head h (256 s x 64 d) transposed into kbuf, async.
// thread: fixed d = tid&63, s = (tid>>6) + 8j. Coalesced global (128B/warp),
// conflict-free smem (bank = (d+s)%32).
__device__ __forceinline__ void prefetch_chunk(float* kbuf, const float* base,
                                               int h, int c, int tid) {
    const int d  = tid & 63;
    const int s0 = tid >> 6;
    const float* g = base + ((size_t)(c * CHUNK) + s0) * DM + h * D + d;
    uint32_t sa = (uint32_t)__cvta_generic_to_shared(kbuf + d * KTS + s0);
    #pragma unroll
    for (int j = 0; j < 32; ++j) {
        cpa4(sa, g);
        sa += 8 * 4;          // s += 8 (floats -> bytes)
        g  += 8 * DM;
    }
    asm volatile("cp.async.commit_group;\n");
}

extern "C" __global__ void __launch_bounds__(THREADS, 1)
attn_fused_kernel(const float* __restrict__ in,
                  float* __restrict__ out,
                  float* __restrict__ attn_out,
                  int write_attn)
{
    extern __shared__ float sm[];
    float* kb0 = sm + SM_K0;
    float* kb1 = sm + SM_K1;
    float* B   = sm + SM_B;      // e values for current chunk, [s][BS] rows of 16 q
    float* qs  = sm + SM_QS;     // [d][16]
    float* atb = sm + SM_AT;     // [16 q][1024 s] e values of current head

    const int qt   = blockIdx.x;
    const int n    = blockIdx.y;
    const int q0   = qt * QT;
    const int tid  = threadIdx.x;
    const int lane = tid & 31;
    const int warp = tid >> 5;       // 16 warps: softmax/attn row owner; PV s-range

    const float* base = in + (size_t)n * L_S * DM;

    // attention head-mean accumulator (warp w owns q-row w): at_acc[j] <-> s=lane+32j
    float at_acc[32];
    #pragma unroll
    for (int j = 0; j < 32; ++j) at_acc[j] = 0.f;

    float2 pv[16];                   // PV partials: pv[q] for dh = (2*lane, 2*lane+1)
    float  Zrow = 0.f;               // softmax denominator for row `warp`

    // prologue: prefetch chunk 0 of head 0
    prefetch_chunk(kb0, base, 0, 0, tid);

    for (int i = 0; i < NITER; ++i) {
        const int h = i >> 2;
        const int c = i & 3;
        float* kcur = (i & 1) ? kb1 : kb0;
        float* knxt = (i & 1) ? kb0 : kb1;

        asm volatile("cp.async.wait_group 0;\n");
        __syncthreads();   // chunk i resident everywhere; prev PV/tail complete

        if (i + 1 < NITER)
            prefetch_chunk(knxt, base, (i + 1) >> 2, (i + 1) & 3, tid);

        if (c == 0) {
            // new head: reset accumulators, load Q tile [d][16] pre-scaled
            #pragma unroll
            for (int q = 0; q < 16; ++q) pv[q] = make_float2(0.f, 0.f);
            Zrow = 0.f;
            #pragma unroll
            for (int it = 0; it < 2; ++it) {
                int idx = it * THREADS + tid;
                int d = idx & 63, ii = idx >> 6;
                qs[d * QT + ii] = base[(size_t)(q0 + ii) * DM + h * D + d] * SCALE;
            }
            __syncthreads();
        }

        // ---- QK^T + exp : thread owns s = tid&255, q-group qg = tid>>8 ----
        {
            const int s  = tid & 255;
            const int qg = tid >> 8;
            const float4* q4 = reinterpret_cast<const float4*>(qs) + qg * 2;
            const float* krow = kcur + s;
            float2 a0 = make_float2(0.f, 0.f), a1 = a0, a2 = a0, a3 = a0;
            #pragma unroll 8
            for (int d = 0; d < D; ++d) {
                const float kv = krow[d * KTS];
                const float2 kk = make_float2(kv, kv);
                const float4 qa = q4[d * 4];
                const float4 qb = q4[d * 4 + 1];
                ffma2(a0, make_float2(qa.x, qa.y), kk);
                ffma2(a1, make_float2(qa.z, qa.w), kk);
                ffma2(a2, make_float2(qb.x, qb.y), kk);
                ffma2(a3, make_float2(qb.z, qb.w), kk);
            }
            // softmax without max-sub (scores ~N(0,1), no overflow risk)
            a0.x = __expf(a0.x); a0.y = __expf(a0.y);
            a1.x = __expf(a1.x); a1.y = __expf(a1.y);
            a2.x = __expf(a2.x); a2.y = __expf(a2.y);
            a3.x = __expf(a3.x); a3.y = __expf(a3.y);
            float2* brow = reinterpret_cast<float2*>(B + s * BS + qg * 8);
            brow[0] = a0; brow[1] = a1; brow[2] = a2; brow[3] = a3;
        }
        __syncthreads();   // B (e values) ready

        // ---- PV: warp owns s in [warp*16, warp*16+16); lane owns dh pair ----
        {
            const int s0 = warp * 16;
            const float* v0 = kcur + (2 * lane) * KTS;
            const float* v1 = v0 + KTS;
            #pragma unroll 2
            for (int j = 0; j < 16; ++j) {
                const int s = s0 + j;
                const float2 v = make_float2(v0[s], v1[s]);
                const float4* p4 = reinterpret_cast<const float4*>(B + s * BS);
                const float4 pa = p4[0], pb = p4[1], pc = p4[2], pd = p4[3];
                ffma2(pv[0],  v, make_float2(pa.x, pa.x));
                ffma2(pv[1],  v, make_float2(pa.y, pa.y));
                ffma2(pv[2],  v, make_float2(pa.z, pa.z));
                ffma2(pv[3],  v, make_float2(pa.w, pa.w));
                ffma2(pv[4],  v, make_float2(pb.x, pb.x));
                ffma2(pv[5],  v, make_float2(pb.y, pb.y));
                ffma2(pv[6],  v, make_float2(pb.z, pb.z));
                ffma2(pv[7],  v, make_float2(pb.w, pb.w));
                ffma2(pv[8],  v, make_float2(pc.x, pc.x));
                ffma2(pv[9],  v, make_float2(pc.y, pc.y));
                ffma2(pv[10], v, make_float2(pc.z, pc.z));
                ffma2(pv[11], v, make_float2(pc.w, pc.w));
                ffma2(pv[12], v, make_float2(pd.x, pd.x));
                ffma2(pv[13], v, make_float2(pd.y, pd.y));
                ffma2(pv[14], v, make_float2(pd.z, pd.z));
                ffma2(pv[15], v, make_float2(pd.w, pd.w));
            }

            // Z partial + stash e row into atb (warp w reads its own q-row)
            float zs = 0.f;
            #pragma unroll
            for (int j = 0; j < 8; ++j) {
                const int s = lane + 32 * j;
                const float e = B[s * BS + warp];
                zs += e;
                atb[warp * L_S + c * CHUNK + s] = e;
            }
            #pragma unroll
            for (int o = 16; o > 0; o >>= 1)
                zs += __shfl_xor_sync(0xffffffffu, zs, o);
            Zrow += zs;
        }

        if (c == 3) {
            // ---- head epilogue: cross-warp PV reduce via kcur, normalize ----
            __syncthreads();                        // all PV reads of kcur done
            float2* red = reinterpret_cast<float2*>(kcur);
            #pragma unroll
            for (int q = 0; q < 16; ++q)
                red[(warp * 16 + q) * 32 + lane] = pv[q];
            __syncthreads();

            const float invZ = 1.0f / Zrow;         // warp-uniform; q-row == warp
            float2 r = make_float2(0.f, 0.f);
            #pragma unroll
            for (int g = 0; g < 16; ++g) {
                const float2 t = red[(g * 16 + warp) * 32 + lane];
                r.x += t.x; r.y += t.y;
            }
            r.x *= invZ; r.y *= invZ;
            *reinterpret_cast<float2*>(
                out + (size_t)(n * L_S + q0 + warp) * DM + h * D + 2 * lane) = r;

            #pragma unroll
            for (int j = 0; j < 32; ++j)
                at_acc[j] += atb[warp * L_S + lane + 32 * j] * invZ;
            // next iteration's top syncthreads protects kcur before reuse
        }
    }

    // ---- head-averaged attention weights (warp w owns row w) ----
    if (write_attn) {
        float* aout = attn_out + ((size_t)n * L_S + q0 + warp) * L_S;
        #pragma unroll
        for (int j = 0; j < 32; ++j)
            aout[lane + 32 * j] = at_acc[j] * (1.f / 16.f);
    }
}

extern "C" void kernel_launch(void* const* d_in, const int* in_sizes, int n_in,
                              void* d_out, int out_size) {
    const float* in = (const float*)d_in[0];
    float* out = (float*)d_out;
    const size_t out_elems  = (size_t)N_B * L_S * DM;       // 8,388,608
    const size_t attn_elems = (size_t)N_B * L_S * L_S;      // 8,388,608
    int write_attn = (out_size >= (int)(out_elems + attn_elems)) ? 1 : 0;
    float* attn = out + out_elems;

    const int smem_bytes = SM_TOT * sizeof(float);          // 221696 B
    cudaFuncSetAttribute(attn_fused_kernel,
                         cudaFuncAttributeMaxDynamicSharedMemorySize, smem_bytes);

    dim3 grid(L_S / QT, N_B);   // (64, 8)
    attn_fused_kernel<<<grid, THREADS, smem_bytes>>>(in, out, attn, write_attn);
}

// round 6
// speedup vs baseline: 2.2469x; 2.2469x over previous
#include <cuda_runtime.h>
#include <cuda_bf16.h>
#include <stdint.h>
#include <math.h>

#define N_B 8
#define L_S 1024
#define DM  1024
#define H   16
#define D   64
#define QB  64
#define CH  128
#define NCH 8
#define THREADS 256
#define SCALE 0.125f

// SMEM byte offsets
#define SO_KH  0                      // K chunk hi: [128 s][64 d] bf16, swizzled (16KB)
#define SO_KL  16384                  // K chunk lo
#define SO_VH  32768                  // V^T hi: [64 d][128 s] bf16, swizzled (16KB)
#define SO_VL  49152                  // V^T lo
#define SO_BNC 65536                  // f32 bounce [128 s][68] (34816B); reused as D-reduce
#define SO_ZS  (65536 + 34816)        // 64 x 2 f32 Z partials (512B)
#define SO_ZI  (SO_ZS + 512)          // 64 f32 invZ
#define SMEM_SZ (SO_ZI + 256)         // 101120 B

__device__ float g_escr[(size_t)128 * QB * L_S];   // 32MB e-scratch

// ---------------- helpers ----------------
__device__ __forceinline__ uint32_t s2u(const void* p) {
    uint32_t a;
    asm("{ .reg .u64 t; cvta.to.shared.u64 t, %1; cvt.u32.u64 %0, t; }" : "=r"(a) : "l"(p));
    return a;
}
__device__ __forceinline__ uint32_t pack_bf16(float lo, float hi) {   // lo -> bits[15:0]
    uint32_t r;
    asm("cvt.rn.bf16x2.f32 %0, %1, %2;" : "=r"(r) : "f"(hi), "f"(lo));
    return r;
}
__device__ __forceinline__ float lowbf(uint32_t w)  { return __uint_as_float(w << 16); }
__device__ __forceinline__ float highbf(uint32_t w) { return __uint_as_float(w & 0xffff0000u); }

#define LDM4(r, ad) \
    asm volatile("ldmatrix.sync.aligned.m8n8.x4.shared.b16 {%0,%1,%2,%3}, [%4];" \
        : "=r"((r)[0]), "=r"((r)[1]), "=r"((r)[2]), "=r"((r)[3]) : "r"(ad))

#define MMA(c, a, b0_, b1_) \
    asm volatile("mma.sync.aligned.m16n8k16.row.col.f32.bf16.bf16.f32 " \
        "{%0,%1,%2,%3}, {%4,%5,%6,%7}, {%8,%9}, {%0,%1,%2,%3};" \
        : "+f"((c)[0]), "+f"((c)[1]), "+f"((c)[2]), "+f"((c)[3]) \
        : "r"((a)[0]), "r"((a)[1]), "r"((a)[2]), "r"((a)[3]), "r"(b0_), "r"(b1_))

__device__ __forceinline__ void cvt_split(float4 v, uint32_t& h0, uint32_t& h1,
                                          uint32_t& l0, uint32_t& l1) {
    h0 = pack_bf16(v.x, v.y);
    h1 = pack_bf16(v.z, v.w);
    l0 = pack_bf16(v.x - lowbf(h0), v.y - highbf(h0));
    l1 = pack_bf16(v.z - lowbf(h1), v.w - highbf(h1));
}

// ---------------- kernel ----------------
extern "C" __global__ void __launch_bounds__(THREADS, 1)
attn_mma_kernel(const float* __restrict__ in, float* __restrict__ out,
                float* __restrict__ attn_out, int write_attn)
{
    extern __shared__ __align__(1024) char smem[];
    const uint32_t sb = s2u(smem);
    float* BNC = (float*)(smem + SO_BNC);
    float* ZS  = (float*)(smem + SO_ZS);
    float* ZI  = (float*)(smem + SO_ZI);

    const int tid  = threadIdx.x;
    const int lane = tid & 31;
    const int warp = tid >> 5;
    const int qw   = warp & 3;        // q-tile group (16 rows)
    const int sw   = warp >> 2;       // s-half (64 cols)
    const int qb   = blockIdx.x, n = blockIdx.y;
    const int q0   = qb * QB;

    const float* base = in + (size_t)n * L_S * DM;
    float* escr = g_escr + ((size_t)(n * 16 + qb)) * QB * L_S;

    const int qr   = qw * 16 + (lane >> 2);   // my C/A-frag row (q)
    const int tig2 = 2 * (lane & 3);          // my col pair base

    for (int h = 0; h < H; ++h) {
        __syncthreads();   // [A] protect tiles/BNC/escr from previous head tail

        // ---- stage Q (64x64, pre-scaled, hi/lo split) into KH/KL rows 0-63 ----
        #pragma unroll
        for (int k = 0; k < 4; ++k) {
            int f4 = k * THREADS + tid;
            int row = f4 >> 4, dq = f4 & 15;
            float4 v = *(const float4*)(base + (size_t)(q0 + row) * DM + h * D + dq * 4);
            v.x *= SCALE; v.y *= SCALE; v.z *= SCALE; v.w *= SCALE;
            uint32_t h0, h1, l0, l1; cvt_split(v, h0, h1, l0, l1);
            uint32_t b = row * 128 + ((dq * 8) ^ ((row & 7) << 4));
            *(uint32_t*)(smem + SO_KH + b)     = h0;
            *(uint32_t*)(smem + SO_KH + b + 4) = h1;
            *(uint32_t*)(smem + SO_KL + b)     = l0;
            *(uint32_t*)(smem + SO_KL + b + 4) = l1;
        }
        __syncthreads();   // [B]

        // ---- load persistent Q fragments (A-operand, 4 ksteps, hi/lo) ----
        uint32_t QHf[4][4], QLf[4][4];
        {
            const uint32_t row = qw * 16 + (lane & 15);
            const uint32_t swz = (row & 7) << 4;
            #pragma unroll
            for (int kk = 0; kk < 4; ++kk) {
                uint32_t col = kk * 32 + ((lane >> 4) << 4);
                uint32_t a = sb + SO_KH + row * 128 + (col ^ swz);
                LDM4(QHf[kk], a);
                LDM4(QLf[kk], a + 16384);
            }
        }

        float Dacc[8][4];
        #pragma unroll
        for (int i = 0; i < 8; ++i)
            #pragma unroll
            for (int j = 0; j < 4; ++j) Dacc[i][j] = 0.f;
        float z0 = 0.f, z1 = 0.f;

        for (int c = 0; c < NCH; ++c) {
            const int s0 = c * CH;
            __syncthreads();   // [C] Q frags read; prev chunk PV done with V tiles

            // ---- stage A: global -> bounce + K tiles (hi/lo) ----
            #pragma unroll
            for (int k = 0; k < 8; ++k) {
                int f4 = k * THREADS + tid;
                int s = f4 >> 4, dq = f4 & 15;
                float4 v = *(const float4*)(base + (size_t)(s0 + s) * DM + h * D + dq * 4);
                *(float4*)(BNC + s * 68 + dq * 4) = v;
                uint32_t h0, h1, l0, l1; cvt_split(v, h0, h1, l0, l1);
                uint32_t b = s * 128 + ((dq * 8) ^ ((s & 7) << 4));
                *(uint32_t*)(smem + SO_KH + b)     = h0;
                *(uint32_t*)(smem + SO_KH + b + 4) = h1;
                *(uint32_t*)(smem + SO_KL + b)     = l0;
                *(uint32_t*)(smem + SO_KL + b + 4) = l1;
            }
            __syncthreads();   // [D]

            // ---- stage B: bounce -> V^T tiles (hi/lo) ----
            #pragma unroll
            for (int k = 0; k < 16; ++k) {
                int widx = k * THREADS + tid;
                int dh = widx >> 6, s2 = widx & 63;
                float f0 = BNC[(2 * s2) * 68 + dh];
                float f1 = BNC[(2 * s2 + 1) * 68 + dh];
                uint32_t hw = pack_bf16(f0, f1);
                uint32_t lw = pack_bf16(f0 - lowbf(hw), f1 - highbf(hw));
                uint32_t b = dh * 256 + ((s2 * 4) ^ ((dh & 7) << 4));
                *(uint32_t*)(smem + SO_VH + b) = hw;
                *(uint32_t*)(smem + SO_VL + b) = lw;
            }
            __syncthreads();   // [E]

            // ---- QK^T: 3-pass bf16 split, S in C-fragments ----
            float acc[8][4];
            #pragma unroll
            for (int i = 0; i < 8; ++i)
                #pragma unroll
                for (int j = 0; j < 4; ++j) acc[i][j] = 0.f;

            #pragma unroll
            for (int np = 0; np < 4; ++np) {
                const uint32_t rowb = sw * 64 + np * 16 + (lane & 7) + ((lane >> 4) << 3);
                const uint32_t rsw = (rowb & 7) << 4;
                #pragma unroll
                for (int kk = 0; kk < 4; ++kk) {
                    uint32_t col = kk * 32 + ((lane >> 3) & 1) * 16;
                    uint32_t ah = sb + SO_KH + rowb * 128 + (col ^ rsw);
                    uint32_t bh[4], bl[4];
                    LDM4(bh, ah);
                    LDM4(bl, ah + 16384);
                    MMA(acc[2 * np],     QHf[kk], bh[0], bh[1]);
                    MMA(acc[2 * np + 1], QHf[kk], bh[2], bh[3]);
                    MMA(acc[2 * np],     QLf[kk], bh[0], bh[1]);
                    MMA(acc[2 * np + 1], QLf[kk], bh[2], bh[3]);
                    MMA(acc[2 * np],     QHf[kk], bl[0], bl[1]);
                    MMA(acc[2 * np + 1], QHf[kk], bl[2], bl[3]);
                }
            }

            // ---- exp, Z accumulation, P-fragment pack, e -> scratch ----
            uint32_t PH[8][2], PL[8][2];
            const int scol = sw * 64 + tig2;
            #pragma unroll
            for (int nt = 0; nt < 8; ++nt) {
                float e0 = __expf(acc[nt][0]);
                float e1 = __expf(acc[nt][1]);
                float e2 = __expf(acc[nt][2]);
                float e3 = __expf(acc[nt][3]);
                z0 += e0 + e1; z1 += e2 + e3;
                uint32_t h0 = pack_bf16(e0, e1);
                uint32_t h1 = pack_bf16(e2, e3);
                PH[nt][0] = h0; PH[nt][1] = h1;
                PL[nt][0] = pack_bf16(e0 - lowbf(h0), e1 - highbf(h0));
                PL[nt][1] = pack_bf16(e2 - lowbf(h1), e3 - highbf(h1));
                const int sg = s0 + scol + nt * 8;
                *(float2*)(escr + (size_t)qr * L_S + sg)       = make_float2(e0, e1);
                *(float2*)(escr + (size_t)(qr + 8) * L_S + sg) = make_float2(e2, e3);
            }

            // ---- PV: 3-pass bf16 split, P from registers, V^T from smem ----
            #pragma unroll
            for (int mp = 0; mp < 4; ++mp) {
                const uint32_t rowv = mp * 16 + (lane & 7) + ((lane >> 4) << 3);
                const uint32_t vsw = (rowv & 7) << 4;
                #pragma unroll
                for (int kk = 0; kk < 4; ++kk) {
                    uint32_t col = sw * 128 + kk * 32 + ((lane >> 3) & 1) * 16;
                    uint32_t av = sb + SO_VH + rowv * 256 + (col ^ vsw);
                    uint32_t vh[4], vl[4];
                    LDM4(vh, av);
                    LDM4(vl, av + 16384);
                    uint32_t aH[4] = {PH[2*kk][0], PH[2*kk][1], PH[2*kk+1][0], PH[2*kk+1][1]};
                    uint32_t aL[4] = {PL[2*kk][0], PL[2*kk][1], PL[2*kk+1][0], PL[2*kk+1][1]};
                    MMA(Dacc[2 * mp],     aH, vh[0], vh[1]);
                    MMA(Dacc[2 * mp + 1], aH, vh[2], vh[3]);
                    MMA(Dacc[2 * mp],     aL, vh[0], vh[1]);
                    MMA(Dacc[2 * mp + 1], aL, vh[2], vh[3]);
                    MMA(Dacc[2 * mp],     aH, vl[0], vl[1]);
                    MMA(Dacc[2 * mp + 1], aH, vl[2], vl[3]);
                }
            }
        }

        // ---- head end: Z reduce ----
        z0 += __shfl_xor_sync(0xffffffffu, z0, 1);
        z0 += __shfl_xor_sync(0xffffffffu, z0, 2);
        z1 += __shfl_xor_sync(0xffffffffu, z1, 1);
        z1 += __shfl_xor_sync(0xffffffffu, z1, 2);
        if ((lane & 3) == 0) {
            ZS[(qw * 16 + (lane >> 2)) * 2 + sw]       = z0;
            ZS[(qw * 16 + (lane >> 2) + 8) * 2 + sw]   = z1;
        }
        __syncthreads();   // [F] Z partials + last chunk's V reads done
        if (tid < 64) ZI[tid] = 1.0f / (ZS[2 * tid] + ZS[2 * tid + 1]);

        // sw=1 warps publish D partials into BNC (reused as reduce buffer)
        if (sw == 1) {
            #pragma unroll
            for (int nt = 0; nt < 8; ++nt) {
                int col = nt * 8 + tig2;
                *(float2*)(BNC + qw * 1024 + (lane >> 2) * 64 + col) =
                    make_float2(Dacc[nt][0], Dacc[nt][1]);
                *(float2*)(BNC + qw * 1024 + ((lane >> 2) + 8) * 64 + col) =
                    make_float2(Dacc[nt][2], Dacc[nt][3]);
            }
        }
        __syncthreads();   // [G]

        // sw=0 warps: reduce, normalize, store O
        if (sw == 0) {
            const float iza = ZI[qw * 16 + (lane >> 2)];
            const float izb = ZI[qw * 16 + (lane >> 2) + 8];
            float* orow0 = out + ((size_t)(n * L_S + q0 + qw * 16 + (lane >> 2))) * DM + h * D;
            float* orow1 = orow0 + (size_t)8 * DM;
            #pragma unroll
            for (int nt = 0; nt < 8; ++nt) {
                int col = nt * 8 + tig2;
                float2 r0 = *(float2*)(BNC + qw * 1024 + (lane >> 2) * 64 + col);
                float2 r1 = *(float2*)(BNC + qw * 1024 + ((lane >> 2) + 8) * 64 + col);
                *(float2*)(orow0 + col) =
                    make_float2((Dacc[nt][0] + r0.x) * iza, (Dacc[nt][1] + r0.y) * iza);
                *(float2*)(orow1 + col) =
                    make_float2((Dacc[nt][2] + r1.x) * izb, (Dacc[nt][3] + r1.y) * izb);
            }
        }

        // ---- attn head-mean accumulate: attn (+)= e * invZ / 16 ----
        if (write_attn) {
            const float4* e4 = (const float4*)escr;
            float4* a4 = (float4*)(attn_out + ((size_t)(n * L_S) + q0) * L_S);
            #pragma unroll 4
            for (int k = 0; k < 64; ++k) {
                int idx = k * THREADS + tid;          // 16384 float4s
                int q = idx >> 8, s4 = idx & 255;
                float iz = ZI[q] * (1.f / 16.f);
                float4 e = e4[(size_t)q * 256 + s4];
                float4 r;
                if (h == 0) {
                    r.x = e.x * iz; r.y = e.y * iz; r.z = e.z * iz; r.w = e.w * iz;
                } else {
                    r = a4[(size_t)q * 256 + s4];
                    r.x += e.x * iz; r.y += e.y * iz; r.z += e.z * iz; r.w += e.w * iz;
                }
                a4[(size_t)q * 256 + s4] = r;
            }
        }
    }
}

extern "C" void kernel_launch(void* const* d_in, const int* in_sizes, int n_in,
                              void* d_out, int out_size) {
    const float* in = (const float*)d_in[0];
    float* out = (float*)d_out;
    const size_t out_elems  = (size_t)N_B * L_S * DM;   // 8,388,608
    const size_t attn_elems = (size_t)N_B * L_S * L_S;  // 8,388,608
    int write_attn = (out_size >= (int)(out_elems + attn_elems)) ? 1 : 0;
    float* attn = out + out_elems;

    cudaFuncSetAttribute(attn_mma_kernel,
                         cudaFuncAttributeMaxDynamicSharedMemorySize, SMEM_SZ);
    dim3 grid(16, 8);   // 128 CTAs
    attn_mma_kernel<<<grid, THREADS, SMEM_SZ>>>(in, out, attn, write_attn);
}

// round 7
// speedup vs baseline: 2.8299x; 1.2595x over previous
#include <cuda_runtime.h>
#include <cuda_bf16.h>
#include <stdint.h>
#include <math.h>

#define N_B 8
#define L_S 1024
#define DM  1024
#define H   16
#define D   64
#define QB  64
#define CH  128
#define THREADS 256
#define SCALE 0.125f

// SMEM byte offsets
#define SO_RAW0 0                      // raw f32 chunk double-buffer (32KB each)
#define SO_RAW1 32768
#define SO_KH   65536                  // K chunk hi: [128 s][64 d] bf16, swizzled (16KB)
#define SO_KL   81920                  // K chunk lo (16KB)
#define SO_QH   98304                  // Q hi: [64 q][64 d] (8KB); +QL = head-end reduce buf
#define SO_QL   106496                 // Q lo (8KB)
#define SO_ZS   114688                 // 64 x 2 f32 Z partials
#define SO_ZI   (SO_ZS + 512)          // 64 f32 invZ
#define SMEM_SZ (SO_ZI + 256)          // 115456 B

__device__ float g_escr[(size_t)128 * QB * L_S];   // 32MB e-scratch

// ---------------- helpers ----------------
__device__ __forceinline__ uint32_t s2u(const void* p) {
    uint32_t a;
    asm("{ .reg .u64 t; cvta.to.shared.u64 t, %1; cvt.u32.u64 %0, t; }" : "=r"(a) : "l"(p));
    return a;
}
__device__ __forceinline__ uint32_t pack_bf16(float lo, float hi) {   // lo -> bits[15:0]
    uint32_t r;
    asm("cvt.rn.bf16x2.f32 %0, %1, %2;" : "=r"(r) : "f"(hi), "f"(lo));
    return r;
}
__device__ __forceinline__ float lowbf(uint32_t w)  { return __uint_as_float(w << 16); }
__device__ __forceinline__ float highbf(uint32_t w) { return __uint_as_float(w & 0xffff0000u); }

#define LDM4(r, ad) \
    asm volatile("ldmatrix.sync.aligned.m8n8.x4.shared.b16 {%0,%1,%2,%3}, [%4];" \
        : "=r"((r)[0]), "=r"((r)[1]), "=r"((r)[2]), "=r"((r)[3]) : "r"(ad))

#define LDM4T(r, ad) \
    asm volatile("ldmatrix.sync.aligned.m8n8.x4.trans.shared.b16 {%0,%1,%2,%3}, [%4];" \
        : "=r"((r)[0]), "=r"((r)[1]), "=r"((r)[2]), "=r"((r)[3]) : "r"(ad))

#define MMA(c, a, b0_, b1_) \
    asm volatile("mma.sync.aligned.m16n8k16.row.col.f32.bf16.bf16.f32 " \
        "{%0,%1,%2,%3}, {%4,%5,%6,%7}, {%8,%9}, {%0,%1,%2,%3};" \
        : "+f"((c)[0]), "+f"((c)[1]), "+f"((c)[2]), "+f"((c)[3]) \
        : "r"((a)[0]), "r"((a)[1]), "r"((a)[2]), "r"((a)[3]), "r"(b0_), "r"(b1_))

#define CPA16(sa, g) \
    asm volatile("cp.async.cg.shared.global [%0], [%1], 16;" :: "r"(sa), "l"(g))
#define CPA_COMMIT() asm volatile("cp.async.commit_group;" ::: "memory")
#define CPA_WAIT0()  asm volatile("cp.async.wait_group 0;" ::: "memory")

__device__ __forceinline__ void cvt_split(float4 v, uint32_t& h0, uint32_t& h1,
                                          uint32_t& l0, uint32_t& l1) {
    h0 = pack_bf16(v.x, v.y);
    h1 = pack_bf16(v.z, v.w);
    l0 = pack_bf16(v.x - lowbf(h0), v.y - highbf(h0));
    l1 = pack_bf16(v.z - lowbf(h1), v.w - highbf(h1));
}

// ---------------- kernel ----------------
extern "C" __global__ void __launch_bounds__(THREADS, 1)
attn_mma_kernel(const float* __restrict__ in, float* __restrict__ out,
                float* __restrict__ attn_out, int write_attn)
{
    extern __shared__ __align__(1024) char smem[];
    const uint32_t sb = s2u(smem);
    float* ZS  = (float*)(smem + SO_ZS);
    float* ZI  = (float*)(smem + SO_ZI);
    float* RED = (float*)(smem + SO_QH);      // head-end reduce buffer (16KB)

    const int tid  = threadIdx.x;
    const int lane = tid & 31;
    const int warp = tid >> 5;
    const int qw   = warp & 3;        // q-tile group (16 rows)
    const int sw   = warp >> 2;       // s-half (64 cols)
    const int qb   = blockIdx.x, n = blockIdx.y;
    const int q0   = qb * QB;

    const float* base = in + (size_t)n * L_S * DM;
    float* escr = g_escr + ((size_t)(n * 16 + qb)) * QB * L_S;

    const int qr   = qw * 16 + (lane >> 2);   // C/A-frag row (q)
    const int tig2 = 2 * (lane & 3);          // col pair base

    // trans-ldmatrix lane geometry for PV B-operand
    const int tg = lane >> 3, tr = lane & 7;
    const uint32_t pv_srow0 = (uint32_t)(sw * 64 + (tg & 1) * 8 + tr);
    const uint32_t pv_dbase = (uint32_t)((tg >> 1) * 8);

    // prologue: prefetch chunk (h=0,c=0) into RAW0
    {
        const uint32_t s0a = sb + SO_RAW0;
        #pragma unroll
        for (int k = 0; k < 8; ++k) {
            int f4 = k * THREADS + tid;
            int s = f4 >> 4, dq = f4 & 15;
            CPA16(s0a + (uint32_t)(s * 256 + dq * 16),
                  base + (size_t)s * DM + dq * 4);
        }
        CPA_COMMIT();
    }

    uint32_t QHf[4][4], QLf[4][4];
    float Dacc[8][4];
    float z0 = 0.f, z1 = 0.f;

    for (int i = 0; i < H * 8; ++i) {
        const int h = i >> 3, c = i & 7;
        const int s0 = c * CH;
        float* raw = (float*)(smem + ((c & 1) ? SO_RAW1 : SO_RAW0));

        CPA_WAIT0();
        __syncthreads();   // raw[c&1] ready for all; tiles free (prev PV done)

        if (c == 0) {
            // ---- stage Q (pre-scaled, hi/lo) into QH/QL ----
            #pragma unroll
            for (int k = 0; k < 4; ++k) {
                int f4 = k * THREADS + tid;
                int row = f4 >> 4, dq = f4 & 15;
                float4 v = *(const float4*)(base + (size_t)(q0 + row) * DM + h * D + dq * 4);
                v.x *= SCALE; v.y *= SCALE; v.z *= SCALE; v.w *= SCALE;
                uint32_t h0, h1, l0, l1; cvt_split(v, h0, h1, l0, l1);
                uint32_t b = row * 128 + ((dq * 8) ^ ((row & 7) << 4));
                *(uint2*)(smem + SO_QH + b) = make_uint2(h0, h1);
                *(uint2*)(smem + SO_QL + b) = make_uint2(l0, l1);
            }
            __syncthreads();
            // ---- persistent Q fragments ----
            const uint32_t row = qw * 16 + (lane & 15);
            const uint32_t swz = (row & 7) << 4;
            #pragma unroll
            for (int kk = 0; kk < 4; ++kk) {
                uint32_t col = kk * 32 + ((lane >> 4) << 4);
                uint32_t a = sb + SO_QH + row * 128 + (col ^ swz);
                LDM4(QHf[kk], a);
                LDM4(QLf[kk], a + 8192);
            }
            #pragma unroll
            for (int x = 0; x < 8; ++x)
                #pragma unroll
                for (int j = 0; j < 4; ++j) Dacc[x][j] = 0.f;
            z0 = 0.f; z1 = 0.f;
        }

        // ---- prefetch chunk i+1 into the other raw buffer ----
        if (i + 1 < H * 8) {
            const int hn = (i + 1) >> 3, cn = (i + 1) & 7;
            const uint32_t dst = sb + ((cn & 1) ? SO_RAW1 : SO_RAW0);
            const float* gsrc = base + (size_t)(cn * CH) * DM + hn * D;
            #pragma unroll
            for (int k = 0; k < 8; ++k) {
                int f4 = k * THREADS + tid;
                int s = f4 >> 4, dq = f4 & 15;
                CPA16(dst + (uint32_t)(s * 256 + dq * 16),
                      gsrc + (size_t)s * DM + dq * 4);
            }
            CPA_COMMIT();
        }

        // ---- cvt raw -> K tiles (hi/lo) ----
        #pragma unroll
        for (int k = 0; k < 8; ++k) {
            int f4 = k * THREADS + tid;
            int s = f4 >> 4, dq = f4 & 15;
            float4 v = *(const float4*)(raw + s * 64 + dq * 4);
            uint32_t h0, h1, l0, l1; cvt_split(v, h0, h1, l0, l1);
            uint32_t b = s * 128 + ((dq * 8) ^ ((s & 7) << 4));
            *(uint2*)(smem + SO_KH + b) = make_uint2(h0, h1);
            *(uint2*)(smem + SO_KL + b) = make_uint2(l0, l1);
        }
        __syncthreads();   // tiles ready

        // ---- QK^T: 3-pass bf16 split ----
        float acc[8][4];
        #pragma unroll
        for (int x = 0; x < 8; ++x)
            #pragma unroll
            for (int j = 0; j < 4; ++j) acc[x][j] = 0.f;

        #pragma unroll
        for (int np = 0; np < 4; ++np) {
            const uint32_t rowb = sw * 64 + np * 16 + (lane & 7) + ((lane >> 4) << 3);
            const uint32_t rsw = (rowb & 7) << 4;
            #pragma unroll
            for (int kk = 0; kk < 4; ++kk) {
                uint32_t col = kk * 32 + ((lane >> 3) & 1) * 16;
                uint32_t ah = sb + SO_KH + rowb * 128 + (col ^ rsw);
                uint32_t bh[4], bl[4];
                LDM4(bh, ah);
                LDM4(bl, ah + 16384);
                MMA(acc[2 * np],     QHf[kk], bh[0], bh[1]);
                MMA(acc[2 * np + 1], QHf[kk], bh[2], bh[3]);
                MMA(acc[2 * np],     QLf[kk], bh[0], bh[1]);
                MMA(acc[2 * np + 1], QLf[kk], bh[2], bh[3]);
                MMA(acc[2 * np],     QHf[kk], bl[0], bl[1]);
                MMA(acc[2 * np + 1], QHf[kk], bl[2], bl[3]);
            }
        }

        // ---- exp, Z accumulate, P-fragment pack, e -> scratch ----
        uint32_t PH[8][2], PL[8][2];
        const int scol = sw * 64 + tig2;
        #pragma unroll
        for (int nt = 0; nt < 8; ++nt) {
            float e0 = __expf(acc[nt][0]);
            float e1 = __expf(acc[nt][1]);
            float e2 = __expf(acc[nt][2]);
            float e3 = __expf(acc[nt][3]);
            z0 += e0 + e1; z1 += e2 + e3;
            uint32_t h0 = pack_bf16(e0, e1);
            uint32_t h1 = pack_bf16(e2, e3);
            PH[nt][0] = h0; PH[nt][1] = h1;
            PL[nt][0] = pack_bf16(e0 - lowbf(h0), e1 - highbf(h0));
            PL[nt][1] = pack_bf16(e2 - lowbf(h1), e3 - highbf(h1));
            const int sg = s0 + scol + nt * 8;
            *(float2*)(escr + (size_t)qr * L_S + sg)       = make_float2(e0, e1);
            *(float2*)(escr + (size_t)(qr + 8) * L_S + sg) = make_float2(e2, e3);
        }

        // ---- PV: B via ldmatrix.trans on the SAME K tiles (V == K) ----
        #pragma unroll
        for (int dt = 0; dt < 4; ++dt) {
            const uint32_t dcol = 2 * (pv_dbase + dt * 16);
            #pragma unroll
            for (int kk = 0; kk < 4; ++kk) {
                const uint32_t srow = pv_srow0 + kk * 16;
                uint32_t av = sb + SO_KH + srow * 128 + (dcol ^ ((uint32_t)tr << 4));
                uint32_t vh[4], vl[4];
                LDM4T(vh, av);
                LDM4T(vl, av + 16384);
                uint32_t aH[4] = {PH[2*kk][0], PH[2*kk][1], PH[2*kk+1][0], PH[2*kk+1][1]};
                uint32_t aL[4] = {PL[2*kk][0], PL[2*kk][1], PL[2*kk+1][0], PL[2*kk+1][1]};
                MMA(Dacc[2 * dt],     aH, vh[0], vh[1]);
                MMA(Dacc[2 * dt + 1], aH, vh[2], vh[3]);
                MMA(Dacc[2 * dt],     aL, vh[0], vh[1]);
                MMA(Dacc[2 * dt + 1], aL, vh[2], vh[3]);
                MMA(Dacc[2 * dt],     aH, vl[0], vl[1]);
                MMA(Dacc[2 * dt + 1], aH, vl[2], vl[3]);
            }
        }

        if (c == 7) {
            // ---- head end: Z reduce ----
            z0 += __shfl_xor_sync(0xffffffffu, z0, 1);
            z0 += __shfl_xor_sync(0xffffffffu, z0, 2);
            z1 += __shfl_xor_sync(0xffffffffu, z1, 1);
            z1 += __shfl_xor_sync(0xffffffffu, z1, 2);
            if ((lane & 3) == 0) {
                ZS[(qw * 16 + (lane >> 2)) * 2 + sw]     = z0;
                ZS[(qw * 16 + (lane >> 2) + 8) * 2 + sw] = z1;
            }
            __syncthreads();   // [F]
            if (tid < 64) ZI[tid] = 1.0f / (ZS[2 * tid] + ZS[2 * tid + 1]);

            if (sw == 1) {     // publish D partials into RED (Q tiles done with)
                #pragma unroll
                for (int nt = 0; nt < 8; ++nt) {
                    int col = nt * 8 + tig2;
                    *(float2*)(RED + qw * 1024 + (lane >> 2) * 64 + col) =
                        make_float2(Dacc[nt][0], Dacc[nt][1]);
                    *(float2*)(RED + qw * 1024 + ((lane >> 2) + 8) * 64 + col) =
                        make_float2(Dacc[nt][2], Dacc[nt][3]);
                }
            }
            __syncthreads();   // [G]

            if (sw == 0) {     // reduce + normalize + store O
                const float iza = ZI[qw * 16 + (lane >> 2)];
                const float izb = ZI[qw * 16 + (lane >> 2) + 8];
                float* orow0 = out + ((size_t)(n * L_S + q0 + qw * 16 + (lane >> 2))) * DM + h * D;
                float* orow1 = orow0 + (size_t)8 * DM;
                #pragma unroll
                for (int nt = 0; nt < 8; ++nt) {
                    int col = nt * 8 + tig2;
                    float2 r0 = *(float2*)(RED + qw * 1024 + (lane >> 2) * 64 + col);
                    float2 r1 = *(float2*)(RED + qw * 1024 + ((lane >> 2) + 8) * 64 + col);
                    *(float2*)(orow0 + col) =
                        make_float2((Dacc[nt][0] + r0.x) * iza, (Dacc[nt][1] + r0.y) * iza);
                    *(float2*)(orow1 + col) =
                        make_float2((Dacc[nt][2] + r1.x) * izb, (Dacc[nt][3] + r1.y) * izb);
                }
            }

            // ---- attn head-mean accumulate: attn (+)= e * invZ / 16 ----
            if (write_attn) {
                const float4* e4 = (const float4*)escr;
                float4* a4 = (float4*)(attn_out + ((size_t)(n * L_S) + q0) * L_S);
                #pragma unroll 4
                for (int k = 0; k < 64; ++k) {
                    int idx = k * THREADS + tid;
                    int q = idx >> 8, s4 = idx & 255;
                    float iz = ZI[q] * (1.f / 16.f);
                    float4 e = e4[(size_t)q * 256 + s4];
                    float4 r;
                    if (h == 0) {
                        r.x = e.x * iz; r.y = e.y * iz; r.z = e.z * iz; r.w = e.w * iz;
                    } else {
                        r = a4[(size_t)q * 256 + s4];
                        r.x += e.x * iz; r.y += e.y * iz; r.z += e.z * iz; r.w += e.w * iz;
                    }
                    a4[(size_t)q * 256 + s4] = r;
                }
            }
        }
    }
}

extern "C" void kernel_launch(void* const* d_in, const int* in_sizes, int n_in,
                              void* d_out, int out_size) {
    const float* in = (const float*)d_in[0];
    float* out = (float*)d_out;
    const size_t out_elems  = (size_t)N_B * L_S * DM;   // 8,388,608
    const size_t attn_elems = (size_t)N_B * L_S * L_S;  // 8,388,608
    int write_attn = (out_size >= (int)(out_elems + attn_elems)) ? 1 : 0;
    float* attn = out + out_elems;

    cudaFuncSetAttribute(attn_mma_kernel,
                         cudaFuncAttributeMaxDynamicSharedMemorySize, SMEM_SZ);
    dim3 grid(16, 8);   // 128 CTAs
    attn_mma_kernel<<<grid, THREADS, SMEM_SZ>>>(in, out, attn, write_attn);
}

// round 8
// speedup vs baseline: 3.0266x; 1.0695x over previous
#include <cuda_runtime.h>
#include <cuda_bf16.h>
#include <stdint.h>
#include <math.h>

#define N_B 8
#define L_S 1024
#define DM  1024
#define H   16
#define D   64
#define QB  64
#define CH  128
#define THREADS 512
#define SCALE 0.125f

// SMEM byte offsets
#define SO_RAW0 0                      // raw f32 chunk double-buffer (32KB each)
#define SO_RAW1 32768
#define SO_KH   65536                  // K chunk hi: [128 s][64 d] bf16, swizzled (16KB)
#define SO_KL   81920                  // K chunk lo (16KB)
#define SO_QH   98304                  // Q hi (8KB); head-end: 3rd D-partial
#define SO_QL   106496                 // Q lo (8KB)
#define SO_ZS   114688                 // 64 x 4 f32 Z partials (1KB)
#define SO_ZI   (SO_ZS + 1024)        // 64 f32 invZ
#define SMEM_SZ (SO_ZI + 256)          // 115968 B

__device__ float g_escr[(size_t)128 * QB * L_S];   // 32MB e-scratch

// ---------------- helpers ----------------
__device__ __forceinline__ uint32_t s2u(const void* p) {
    uint32_t a;
    asm("{ .reg .u64 t; cvta.to.shared.u64 t, %1; cvt.u32.u64 %0, t; }" : "=r"(a) : "l"(p));
    return a;
}
__device__ __forceinline__ uint32_t pack_bf16(float lo, float hi) {   // lo -> bits[15:0]
    uint32_t r;
    asm("cvt.rn.bf16x2.f32 %0, %1, %2;" : "=r"(r) : "f"(hi), "f"(lo));
    return r;
}
__device__ __forceinline__ float lowbf(uint32_t w)  { return __uint_as_float(w << 16); }
__device__ __forceinline__ float highbf(uint32_t w) { return __uint_as_float(w & 0xffff0000u); }

#define LDM4(r, ad) \
    asm volatile("ldmatrix.sync.aligned.m8n8.x4.shared.b16 {%0,%1,%2,%3}, [%4];" \
        : "=r"((r)[0]), "=r"((r)[1]), "=r"((r)[2]), "=r"((r)[3]) : "r"(ad))

#define LDM4T(r, ad) \
    asm volatile("ldmatrix.sync.aligned.m8n8.x4.trans.shared.b16 {%0,%1,%2,%3}, [%4];" \
        : "=r"((r)[0]), "=r"((r)[1]), "=r"((r)[2]), "=r"((r)[3]) : "r"(ad))

#define MMA(c, a, b0_, b1_) \
    asm volatile("mma.sync.aligned.m16n8k16.row.col.f32.bf16.bf16.f32 " \
        "{%0,%1,%2,%3}, {%4,%5,%6,%7}, {%8,%9}, {%0,%1,%2,%3};" \
        : "+f"((c)[0]), "+f"((c)[1]), "+f"((c)[2]), "+f"((c)[3]) \
        : "r"((a)[0]), "r"((a)[1]), "r"((a)[2]), "r"((a)[3]), "r"(b0_), "r"(b1_))

#define CPA16(sa, g) \
    asm volatile("cp.async.cg.shared.global [%0], [%1], 16;" :: "r"(sa), "l"(g))
#define CPA_COMMIT() asm volatile("cp.async.commit_group;" ::: "memory")
#define CPA_WAIT0()  asm volatile("cp.async.wait_group 0;" ::: "memory")

__device__ __forceinline__ void cvt_split(float4 v, uint32_t& h0, uint32_t& h1,
                                          uint32_t& l0, uint32_t& l1) {
    h0 = pack_bf16(v.x, v.y);
    h1 = pack_bf16(v.z, v.w);
    l0 = pack_bf16(v.x - lowbf(h0), v.y - highbf(h0));
    l1 = pack_bf16(v.z - lowbf(h1), v.w - highbf(h1));
}

// ---------------- kernel ----------------
extern "C" __global__ void __launch_bounds__(THREADS)
attn_mma_kernel(const float* __restrict__ in, float* __restrict__ out,
                float* __restrict__ attn_out, int write_attn)
{
    extern __shared__ __align__(1024) char smem[];
    const uint32_t sb = s2u(smem);
    float* ZS = (float*)(smem + SO_ZS);
    float* ZI = (float*)(smem + SO_ZI);
    float* P1 = (float*)(smem + SO_RAW1);            // 16KB D-partial (sw=1)
    float* P2 = (float*)(smem + SO_RAW1 + 16384);    // 16KB D-partial (sw=2)
    float* P3 = (float*)(smem + SO_QH);              // 16KB D-partial (sw=3)

    const int tid  = threadIdx.x;
    const int lane = tid & 31;
    const int warp = tid >> 5;        // 16 warps
    const int qw   = warp & 3;        // q-tile group (16 rows)
    const int sw   = warp >> 2;       // s-quarter (32 cols)
    const int qb   = blockIdx.x, n = blockIdx.y;
    const int q0   = qb * QB;

    const float* base = in + (size_t)n * L_S * DM;
    float* escr = g_escr + ((size_t)(n * 16 + qb)) * QB * L_S;

    const int qr   = qw * 16 + (lane >> 2);   // C/A-frag row (q)
    const int tig2 = 2 * (lane & 3);          // col pair base

    // trans-ldmatrix lane geometry for PV B-operand
    const int tg = lane >> 3, tr = lane & 7;
    const uint32_t pv_srow0 = (uint32_t)(sw * 32 + (tg & 1) * 8 + tr);
    const uint32_t pv_dbase = (uint32_t)((tg >> 1) * 8);

    // prologue: prefetch chunk (h=0,c=0) into RAW0
    {
        const uint32_t s0a = sb + SO_RAW0;
        #pragma unroll
        for (int k = 0; k < 4; ++k) {
            int f4 = k * THREADS + tid;
            int s = f4 >> 4, dq = f4 & 15;
            CPA16(s0a + (uint32_t)(s * 256 + dq * 16),
                  base + (size_t)s * DM + dq * 4);
        }
        CPA_COMMIT();
    }

    uint32_t QHf[4][4], QLf[4][4];
    float Dacc[8][4];
    float z0 = 0.f, z1 = 0.f;

    for (int i = 0; i < H * 8; ++i) {
        const int h = i >> 3, c = i & 7;
        const int s0 = c * CH;
        float* raw = (float*)(smem + ((c & 1) ? SO_RAW1 : SO_RAW0));

        CPA_WAIT0();
        __syncthreads();   // raw[c&1] ready; tiles + reduce buffers free

        if (c == 0) {
            // ---- stage Q (pre-scaled, hi/lo) into QH/QL ----
            #pragma unroll
            for (int k = 0; k < 2; ++k) {
                int f4 = k * THREADS + tid;
                int row = f4 >> 4, dq = f4 & 15;
                float4 v = *(const float4*)(base + (size_t)(q0 + row) * DM + h * D + dq * 4);
                v.x *= SCALE; v.y *= SCALE; v.z *= SCALE; v.w *= SCALE;
                uint32_t h0, h1, l0, l1; cvt_split(v, h0, h1, l0, l1);
                uint32_t b = row * 128 + ((dq * 8) ^ ((row & 7) << 4));
                *(uint2*)(smem + SO_QH + b) = make_uint2(h0, h1);
                *(uint2*)(smem + SO_QL + b) = make_uint2(l0, l1);
            }
            __syncthreads();
            // ---- persistent Q fragments ----
            const uint32_t row = qw * 16 + (lane & 15);
            const uint32_t swz = (row & 7) << 4;
            #pragma unroll
            for (int kk = 0; kk < 4; ++kk) {
                uint32_t col = kk * 32 + ((lane >> 4) << 4);
                uint32_t a = sb + SO_QH + row * 128 + (col ^ swz);
                LDM4(QHf[kk], a);
                LDM4(QLf[kk], a + 8192);
            }
            #pragma unroll
            for (int x = 0; x < 8; ++x)
                #pragma unroll
                for (int j = 0; j < 4; ++j) Dacc[x][j] = 0.f;
            z0 = 0.f; z1 = 0.f;
        }

        // ---- prefetch chunk i+1 into the other raw buffer ----
        if (i + 1 < H * 8) {
            const int hn = (i + 1) >> 3, cn = (i + 1) & 7;
            const uint32_t dst = sb + ((cn & 1) ? SO_RAW1 : SO_RAW0);
            const float* gsrc = base + (size_t)(cn * CH) * DM + hn * D;
            #pragma unroll
            for (int k = 0; k < 4; ++k) {
                int f4 = k * THREADS + tid;
                int s = f4 >> 4, dq = f4 & 15;
                CPA16(dst + (uint32_t)(s * 256 + dq * 16),
                      gsrc + (size_t)s * DM + dq * 4);
            }
            CPA_COMMIT();
        }

        // ---- cvt raw -> K tiles (hi/lo) ----
        #pragma unroll
        for (int k = 0; k < 4; ++k) {
            int f4 = k * THREADS + tid;
            int s = f4 >> 4, dq = f4 & 15;
            float4 v = *(const float4*)(raw + s * 64 + dq * 4);
            uint32_t h0, h1, l0, l1; cvt_split(v, h0, h1, l0, l1);
            uint32_t b = s * 128 + ((dq * 8) ^ ((s & 7) << 4));
            *(uint2*)(smem + SO_KH + b) = make_uint2(h0, h1);
            *(uint2*)(smem + SO_KL + b) = make_uint2(l0, l1);
        }
        __syncthreads();   // tiles ready

        // ---- QK^T: 3-pass bf16 split; warp covers 16q x 32s ----
        float acc[4][4];
        #pragma unroll
        for (int x = 0; x < 4; ++x)
            #pragma unroll
            for (int j = 0; j < 4; ++j) acc[x][j] = 0.f;

        #pragma unroll
        for (int np = 0; np < 2; ++np) {
            const uint32_t rowb = sw * 32 + np * 16 + (lane & 7) + ((lane >> 4) << 3);
            const uint32_t rsw = (rowb & 7) << 4;
            #pragma unroll
            for (int kk = 0; kk < 4; ++kk) {
                uint32_t col = kk * 32 + ((lane >> 3) & 1) * 16;
                uint32_t ah = sb + SO_KH + rowb * 128 + (col ^ rsw);
                uint32_t bh[4], bl[4];
                LDM4(bh, ah);
                LDM4(bl, ah + 16384);
                MMA(acc[2 * np],     QHf[kk], bh[0], bh[1]);
                MMA(acc[2 * np + 1], QHf[kk], bh[2], bh[3]);
                MMA(acc[2 * np],     QLf[kk], bh[0], bh[1]);
                MMA(acc[2 * np + 1], QLf[kk], bh[2], bh[3]);
                MMA(acc[2 * np],     QHf[kk], bl[0], bl[1]);
                MMA(acc[2 * np + 1], QHf[kk], bl[2], bl[3]);
            }
        }

        // ---- exp, Z accumulate, P-fragment pack, e -> scratch ----
        uint32_t PH[4][2], PL[4][2];
        const int scol = sw * 32 + tig2;
        #pragma unroll
        for (int nt = 0; nt < 4; ++nt) {
            float e0 = __expf(acc[nt][0]);
            float e1 = __expf(acc[nt][1]);
            float e2 = __expf(acc[nt][2]);
            float e3 = __expf(acc[nt][3]);
            z0 += e0 + e1; z1 += e2 + e3;
            uint32_t h0 = pack_bf16(e0, e1);
            uint32_t h1 = pack_bf16(e2, e3);
            PH[nt][0] = h0; PH[nt][1] = h1;
            PL[nt][0] = pack_bf16(e0 - lowbf(h0), e1 - highbf(h0));
            PL[nt][1] = pack_bf16(e2 - lowbf(h1), e3 - highbf(h1));
            const int sg = s0 + scol + nt * 8;
            *(float2*)(escr + (size_t)qr * L_S + sg)       = make_float2(e0, e1);
            *(float2*)(escr + (size_t)(qr + 8) * L_S + sg) = make_float2(e2, e3);
        }

        // ---- PV: B via ldmatrix.trans on the SAME K tiles (V == K) ----
        #pragma unroll
        for (int dt = 0; dt < 4; ++dt) {
            const uint32_t dcol = 2 * (pv_dbase + dt * 16);
            #pragma unroll
            for (int kk = 0; kk < 2; ++kk) {
                const uint32_t srow = pv_srow0 + kk * 16;
                uint32_t av = sb + SO_KH + srow * 128 + (dcol ^ ((uint32_t)tr << 4));
                uint32_t vh[4], vl[4];
                LDM4T(vh, av);
                LDM4T(vl, av + 16384);
                uint32_t aH[4] = {PH[2*kk][0], PH[2*kk][1], PH[2*kk+1][0], PH[2*kk+1][1]};
                uint32_t aL[4] = {PL[2*kk][0], PL[2*kk][1], PL[2*kk+1][0], PL[2*kk+1][1]};
                MMA(Dacc[2 * dt],     aH, vh[0], vh[1]);
                MMA(Dacc[2 * dt + 1], aH, vh[2], vh[3]);
                MMA(Dacc[2 * dt],     aL, vh[0], vh[1]);
                MMA(Dacc[2 * dt + 1], aL, vh[2], vh[3]);
                MMA(Dacc[2 * dt],     aH, vl[0], vl[1]);
                MMA(Dacc[2 * dt + 1], aH, vl[2], vl[3]);
            }
        }

        if (c == 7) {
            // ---- head end: Z reduce (4 s-quarters per row) ----
            z0 += __shfl_xor_sync(0xffffffffu, z0, 1);
            z0 += __shfl_xor_sync(0xffffffffu, z0, 2);
            z1 += __shfl_xor_sync(0xffffffffu, z1, 1);
            z1 += __shfl_xor_sync(0xffffffffu, z1, 2);
            if ((lane & 3) == 0) {
                ZS[(qw * 16 + (lane >> 2)) * 4 + sw]     = z0;
                ZS[(qw * 16 + (lane >> 2) + 8) * 4 + sw] = z1;
            }
            __syncthreads();   // [F] Z partials in; last chunk tile reads done
            if (tid < 64)
                ZI[tid] = 1.0f / (ZS[4 * tid] + ZS[4 * tid + 1]
                                + ZS[4 * tid + 2] + ZS[4 * tid + 3]);

            // sw=1,2,3 publish D partials (RAW1 + Q region are free now)
            if (sw != 0) {
                float* P = (sw == 1) ? P1 : (sw == 2) ? P2 : P3;
                #pragma unroll
                for (int nt = 0; nt < 8; ++nt) {
                    int col = nt * 8 + tig2;
                    *(float2*)(P + qw * 1024 + (lane >> 2) * 64 + col) =
                        make_float2(Dacc[nt][0], Dacc[nt][1]);
                    *(float2*)(P + qw * 1024 + ((lane >> 2) + 8) * 64 + col) =
                        make_float2(Dacc[nt][2], Dacc[nt][3]);
                }
            }
            __syncthreads();   // [G]

            if (sw == 0) {     // reduce 4 partials + normalize + store O
                const float iza = ZI[qw * 16 + (lane >> 2)];
                const float izb = ZI[qw * 16 + (lane >> 2) + 8];
                float* orow0 = out + ((size_t)(n * L_S + q0 + qw * 16 + (lane >> 2))) * DM + h * D;
                float* orow1 = orow0 + (size_t)8 * DM;
                #pragma unroll
                for (int nt = 0; nt < 8; ++nt) {
                    int col = nt * 8 + tig2;
                    int o0 = qw * 1024 + (lane >> 2) * 64 + col;
                    int o1 = qw * 1024 + ((lane >> 2) + 8) * 64 + col;
                    float2 a1 = *(float2*)(P1 + o0), b1 = *(float2*)(P1 + o1);
                    float2 a2 = *(float2*)(P2 + o0), b2 = *(float2*)(P2 + o1);
                    float2 a3 = *(float2*)(P3 + o0), b3 = *(float2*)(P3 + o1);
                    *(float2*)(orow0 + col) = make_float2(
                        (Dacc[nt][0] + a1.x + a2.x + a3.x) * iza,
                        (Dacc[nt][1] + a1.y + a2.y + a3.y) * iza);
                    *(float2*)(orow1 + col) = make_float2(
                        (Dacc[nt][2] + b1.x + b2.x + b3.x) * izb,
                        (Dacc[nt][3] + b1.y + b2.y + b3.y) * izb);
                }
            }

            // ---- attn head-mean accumulate: attn (+)= e * invZ / 16 ----
            if (write_attn) {
                const float4* e4 = (const float4*)escr;
                float4* a4 = (float4*)(attn_out + ((size_t)(n * L_S) + q0) * L_S);
                #pragma unroll 4
                for (int k = 0; k < 32; ++k) {
                    int idx = k * THREADS + tid;          // 16384 float4s
                    int q = idx >> 8, s4 = idx & 255;
                    float iz = ZI[q] * (1.f / 16.f);
                    float4 e = e4[(size_t)q * 256 + s4];
                    float4 r;
                    if (h == 0) {
                        r.x = e.x * iz; r.y = e.y * iz; r.z = e.z * iz; r.w = e.w * iz;
                    } else {
                        r = a4[(size_t)q * 256 + s4];
                        r.x += e.x * iz; r.y += e.y * iz; r.z += e.z * iz; r.w += e.w * iz;
                    }
                    a4[(size_t)q * 256 + s4] = r;
                }
            }
        }
    }
}

extern "C" void kernel_launch(void* const* d_in, const int* in_sizes, int n_in,
                              void* d_out, int out_size) {
    const float* in = (const float*)d_in[0];
    float* out = (float*)d_out;
    const size_t out_elems  = (size_t)N_B * L_S * DM;   // 8,388,608
    const size_t attn_elems = (size_t)N_B * L_S * L_S;  // 8,388,608
    int write_attn = (out_size >= (int)(out_elems + attn_elems)) ? 1 : 0;
    float* attn = out + out_elems;

    cudaFuncSetAttribute(attn_mma_kernel,
                         cudaFuncAttributeMaxDynamicSharedMemorySize, SMEM_SZ);
    dim3 grid(16, 8);   // 128 CTAs, 512 threads (16 warps)
    attn_mma_kernel<<<grid, THREADS, SMEM_SZ>>>(in, out, attn, write_attn);
}

// round 10
// speedup vs baseline: 4.0923x; 1.3521x over previous
#include <cuda_runtime.h>
#include <cuda_bf16.h>
#include <cuda_fp16.h>
#include <stdint.h>
#include <math.h>

#define N_B 8
#define L_S 1024
#define DM  1024
#define H   16
#define D   64
#define QB  64
#define CH  128
#define THREADS 512
// fold 1/sqrt(64) into exp: exp(0.125*S - m) = ex2(S*EXP_C - m2)
#define EXP_C 0.18033688011112042f
#define LOG2E 1.4426950408889634f

// SMEM byte offsets: double-buffered tile pairs + Q tiles
#define SO_KH0 0          // pair0 hi (16KB); lo at +16384
#define SO_KH1 32768      // pair1 hi; lo at +16384
#define SO_QH  65536      // Q hi (8KB); lo at +8192
#define SO_ZS  81920      // 64 x 4 f32 Z partials (1KB)
#define SO_ZI  82944      // 64 f32 invZ
#define SMEM_SZ 83200

// pre-split bf16 tile images (exact smem byte layout), 16KB per (n,h,c) tile
__device__ char     g_hi[(size_t)16 << 20];                  // 16MB
__device__ char     g_lo[(size_t)16 << 20];                  // 16MB
__device__ uint32_t g_p16[(size_t)16 * 128 * 64 * 512];      // 256MB fp16x2 e-planes
__device__ float    g_invZ[16 * 128 * 64];                   // 512KB

// ---------------- helpers ----------------
__device__ __forceinline__ uint32_t s2u(const void* p) {
    uint32_t a;
    asm("{ .reg .u64 t; cvta.to.shared.u64 t, %1; cvt.u32.u64 %0, t; }" : "=r"(a) : "l"(p));
    return a;
}
__device__ __forceinline__ uint32_t pack_bf16(float lo, float hi) {   // lo -> bits[15:0]
    uint32_t r;
    asm("cvt.rn.bf16x2.f32 %0, %1, %2;" : "=r"(r) : "f"(hi), "f"(lo));
    return r;
}
__device__ __forceinline__ uint32_t pack_f16(float lo, float hi) {    // lo -> bits[15:0]
    uint32_t r;
    asm("cvt.rn.f16x2.f32 %0, %1, %2;" : "=r"(r) : "f"(hi), "f"(lo));
    return r;
}
__device__ __forceinline__ float lowbf(uint32_t w)  { return __uint_as_float(w << 16); }
__device__ __forceinline__ float highbf(uint32_t w) { return __uint_as_float(w & 0xffff0000u); }
__device__ __forceinline__ float exps(float x, float m2) {   // exp(0.125*x) * 2^-m2
    float r, t = fmaf(x, EXP_C, -m2);
    asm("ex2.approx.ftz.f32 %0, %1;" : "=f"(r) : "f"(t));
    return r;
}

#define LDM4(r, ad) \
    asm volatile("ldmatrix.sync.aligned.m8n8.x4.shared.b16 {%0,%1,%2,%3}, [%4];" \
        : "=r"((r)[0]), "=r"((r)[1]), "=r"((r)[2]), "=r"((r)[3]) : "r"(ad))

#define LDM4T(r, ad) \
    asm volatile("ldmatrix.sync.aligned.m8n8.x4.trans.shared.b16 {%0,%1,%2,%3}, [%4];" \
        : "=r"((r)[0]), "=r"((r)[1]), "=r"((r)[2]), "=r"((r)[3]) : "r"(ad))

#define MMA(c, a, b0_, b1_) \
    asm volatile("mma.sync.aligned.m16n8k16.row.col.f32.bf16.bf16.f32 " \
        "{%0,%1,%2,%3}, {%4,%5,%6,%7}, {%8,%9}, {%0,%1,%2,%3};" \
        : "+f"((c)[0]), "+f"((c)[1]), "+f"((c)[2]), "+f"((c)[3]) \
        : "r"((a)[0]), "r"((a)[1]), "r"((a)[2]), "r"((a)[3]), "r"(b0_), "r"(b1_))

#define CPA16(sa, g) \
    asm volatile("cp.async.cg.shared.global [%0], [%1], 16;" :: "r"(sa), "l"(g))
#define CPA_COMMIT() asm volatile("cp.async.commit_group;" ::: "memory")
#define CPA_WAIT0()  asm volatile("cp.async.wait_group 0;" ::: "memory")
#define CPA_WAIT1()  asm volatile("cp.async.wait_group 1;" ::: "memory")

__device__ __forceinline__ void cvt_split(float4 v, uint32_t& h0, uint32_t& h1,
                                          uint32_t& l0, uint32_t& l1) {
    h0 = pack_bf16(v.x, v.y);
    h1 = pack_bf16(v.z, v.w);
    l0 = pack_bf16(v.x - lowbf(h0), v.y - highbf(h0));
    l1 = pack_bf16(v.z - lowbf(h1), v.w - highbf(h1));
}

// ---------------- preprocess: f32 -> bf16 hi/lo tile images ----------------
extern "C" __global__ void __launch_bounds__(512)
prep_kernel(const float* __restrict__ in)
{
    int idx = blockIdx.x * 512 + threadIdx.x;     // 2M threads, 1 float4 each
    int dqi = idx & 255;                          // h*16 + dq
    int s   = (idx >> 8) & 1023;
    int n   = idx >> 18;
    int h = dqi >> 4, dq = dqi & 15;
    float4 v = *(const float4*)(in + (((size_t)(n * 1024 + s)) << 10) + dqi * 4);
    uint32_t h0, h1, l0, l1; cvt_split(v, h0, h1, l0, l1);
    uint32_t t = (uint32_t)((n * 16 + h) * 8 + (s >> 7));
    uint32_t b = (uint32_t)((s & 127) * 128 + ((dq * 8) ^ ((s & 7) << 4)));
    *(uint2*)(g_hi + (((size_t)t) << 14) + b) = make_uint2(h0, h1);
    *(uint2*)(g_lo + (((size_t)t) << 14) + b) = make_uint2(l0, l1);
}

// ---------------- merge: attn = (1/16) sum_h e'_h * invZ'_h ----------------
extern "C" __global__ void __launch_bounds__(256)
merge_kernel(float* __restrict__ attn)
{
    int idx = blockIdx.x * 256 + threadIdx.x;     // 4.19M threads, 2 s each
    int s2 = idx & 511;
    int qg = (idx >> 9) & 1023;
    int n  = idx >> 19;
    int cta = n * 16 + (qg >> 6);
    int ql  = qg & 63;
    float ax = 0.f, ay = 0.f;
    #pragma unroll
    for (int h = 0; h < 16; ++h) {
        int base = (h * 128 + cta) * 64 + ql;
        uint32_t w = g_p16[(((size_t)base) << 9) + s2];
        float iz = g_invZ[base];
        __half2 h2 = *reinterpret_cast<__half2*>(&w);
        float2 v = __half22float2(h2);
        ax += v.x * iz; ay += v.y * iz;
    }
    ((float2*)attn)[idx] = make_float2(ax * (1.f / 16.f), ay * (1.f / 16.f));
}

// ---------------- main attention kernel ----------------
extern "C" __global__ void __launch_bounds__(THREADS)
attn_mma_kernel(float* __restrict__ out)
{
    extern __shared__ __align__(1024) char smem[];
    const uint32_t sb = s2u(smem);
    float* ZS = (float*)(smem + SO_ZS);
    float* ZI = (float*)(smem + SO_ZI);
    float* P1 = (float*)(smem + SO_KH1);          // head-end D-partials (pair1 free)
    float* P2 = (float*)(smem + SO_KH1 + 16384);
    float* P3 = (float*)(smem + SO_QH);

    const int tid  = threadIdx.x;
    const int lane = tid & 31;
    const int warp = tid >> 5;        // 16 warps
    const int qw   = warp & 3;        // q-tile group (16 rows)
    const int sw   = warp >> 2;       // s-quarter (32 cols)
    const int qb   = blockIdx.x, n = blockIdx.y;
    const int q0   = qb * QB;
    const int cta  = n * 16 + qb;

    const int qr   = qw * 16 + (lane >> 2);   // C/A-frag row (q)
    const int tig2 = 2 * (lane & 3);          // col pair base

    // trans-ldmatrix lane geometry for PV B-operand
    const int tg = lane >> 3, tr = lane & 7;
    const uint32_t pv_srow0 = (uint32_t)(sw * 32 + (tg & 1) * 8 + tr);
    const uint32_t pv_dbase = (uint32_t)((tg >> 1) * 8);

    // prologue: prefetch chunk (h=0,c=0) tile pair into pair0
    {
        const size_t tb = ((size_t)(n * 16 * 8)) << 14;     // tile (n,0,0)
        #pragma unroll
        for (int k = 0; k < 2; ++k) {
            uint32_t o = (uint32_t)(k * 512 + tid) * 16;
            CPA16(sb + SO_KH0 + o,         g_hi + tb + o);
            CPA16(sb + SO_KH0 + 16384 + o, g_lo + tb + o);
        }
        CPA_COMMIT();
    }

    uint32_t QHf[4][4], QLf[4][4];
    float Dacc[8][4];
    float z0 = 0.f, z1 = 0.f;
    float m2a = 0.f, m2b = 0.f;       // per-row exp shift (log2 units)
    size_t pbase = 0;

    for (int i = 0; i < H * 8; ++i) {
        const int h = i >> 3, c = i & 7;
        const int s0 = c * CH;
        const uint32_t kb = (i & 1) ? SO_KH1 : SO_KH0;

        CPA_WAIT0();
        __syncthreads();   // cur tiles resident; P-buffers / Q region free

        if (c == 0) {
            // ---- Q tile images (8KB hi + 8KB lo), own cp.async group ----
            const size_t tq = ((size_t)((n * 16 + h) * 8 + (qb >> 1))) << 14;
            const size_t qoff = (size_t)(qb & 1) * 8192;
            CPA16(sb + SO_QH + (uint32_t)tid * 16,        g_hi + tq + qoff + tid * 16);
            CPA16(sb + SO_QH + 8192 + (uint32_t)tid * 16, g_lo + tq + qoff + tid * 16);
            CPA_COMMIT();
        }

        // ---- prefetch chunk i+1 into the other pair ----
        if (i + 1 < H * 8) {
            const uint32_t dkb = ((i + 1) & 1) ? SO_KH1 : SO_KH0;
            const size_t tt = ((size_t)((n * 16 + ((i + 1) >> 3)) * 8 + ((i + 1) & 7))) << 14;
            #pragma unroll
            for (int k = 0; k < 2; ++k) {
                uint32_t o = (uint32_t)(k * 512 + tid) * 16;
                CPA16(sb + dkb + o,         g_hi + tt + o);
                CPA16(sb + dkb + 16384 + o, g_lo + tt + o);
            }
            CPA_COMMIT();
        }

        if (c == 0) {
            CPA_WAIT1();       // Q group (older) done; chunk prefetch may fly
            __syncthreads();
            // ---- persistent Q fragments ----
            const uint32_t row = qw * 16 + (lane & 15);
            const uint32_t swz = (row & 7) << 4;
            #pragma unroll
            for (int kk = 0; kk < 4; ++kk) {
                uint32_t col = kk * 32 + ((lane >> 4) << 4);
                uint32_t a = sb + SO_QH + row * 128 + (col ^ swz);
                LDM4(QHf[kk], a);
                LDM4(QLf[kk], a + 8192);
            }
            // ---- per-row shift: m2 = 0.125*|q_row|^2 * log2(e) ----
            {
                float sa = 0.f, sbq = 0.f;
                const int r0 = qr, r1 = qr + 8;
                #pragma unroll
                for (int t = 0; t < 4; ++t) {
                    int dq = (lane & 3) * 4 + t;     // quad index 0..15
                    uint32_t b0 = r0 * 128 + ((dq * 8) ^ ((r0 & 7) << 4));
                    uint32_t b1 = r1 * 128 + ((dq * 8) ^ ((r1 & 7) << 4));
                    uint2 hw0 = *(uint2*)(smem + SO_QH + b0);
                    uint2 lw0 = *(uint2*)(smem + SO_QH + 8192 + b0);
                    uint2 hw1 = *(uint2*)(smem + SO_QH + b1);
                    uint2 lw1 = *(uint2*)(smem + SO_QH + 8192 + b1);
                    float f0 = lowbf(hw0.x) + lowbf(lw0.x);
                    float f1 = highbf(hw0.x) + highbf(lw0.x);
                    float f2 = lowbf(hw0.y) + lowbf(lw0.y);
                    float f3 = highbf(hw0.y) + highbf(lw0.y);
                    sa += f0 * f0 + f1 * f1 + f2 * f2 + f3 * f3;
                    float g0 = lowbf(hw1.x) + lowbf(lw1.x);
                    float g1 = highbf(hw1.x) + highbf(lw1.x);
                    float g2 = lowbf(hw1.y) + lowbf(lw1.y);
                    float g3 = highbf(hw1.y) + highbf(lw1.y);
                    sbq += g0 * g0 + g1 * g1 + g2 * g2 + g3 * g3;
                }
                sa  += __shfl_xor_sync(0xffffffffu, sa, 1);
                sa  += __shfl_xor_sync(0xffffffffu, sa, 2);
                sbq += __shfl_xor_sync(0xffffffffu, sbq, 1);
                sbq += __shfl_xor_sync(0xffffffffu, sbq, 2);
                m2a = sa  * (0.125f * LOG2E);
                m2b = sbq * (0.125f * LOG2E);
            }
            #pragma unroll
            for (int x = 0; x < 8; ++x)
                #pragma unroll
                for (int j = 0; j < 4; ++j) Dacc[x][j] = 0.f;
            z0 = 0.f; z1 = 0.f;
            pbase = ((size_t)(h * 128 + cta)) << 15;
        }

        // ---- QK^T: 3-pass bf16 split; warp covers 16q x 32s ----
        float acc[4][4];
        #pragma unroll
        for (int x = 0; x < 4; ++x)
            #pragma unroll
            for (int j = 0; j < 4; ++j) acc[x][j] = 0.f;

        #pragma unroll
        for (int np = 0; np < 2; ++np) {
            const uint32_t rowb = sw * 32 + np * 16 + (lane & 7) + ((lane >> 4) << 3);
            const uint32_t rsw = (rowb & 7) << 4;
            #pragma unroll
            for (int kk = 0; kk < 4; ++kk) {
                uint32_t col = kk * 32 + ((lane >> 3) & 1) * 16;
                uint32_t ah = sb + kb + rowb * 128 + (col ^ rsw);
                uint32_t bh[4], bl[4];
                LDM4(bh, ah);
                LDM4(bl, ah + 16384);
                MMA(acc[2 * np],     QHf[kk], bh[0], bh[1]);
                MMA(acc[2 * np + 1], QHf[kk], bh[2], bh[3]);
                MMA(acc[2 * np],     QLf[kk], bh[0], bh[1]);
                MMA(acc[2 * np + 1], QLf[kk], bh[2], bh[3]);
                MMA(acc[2 * np],     QHf[kk], bl[0], bl[1]);
                MMA(acc[2 * np + 1], QHf[kk], bl[2], bl[3]);
            }
        }

        // ---- shifted exp, Z accumulate, P pack, e' -> fp16 planes ----
        uint32_t PH[4][2], PL[4][2];
        const int scol = sw * 32 + tig2;
        #pragma unroll
        for (int nt = 0; nt < 4; ++nt) {
            float e0 = exps(acc[nt][0], m2a);
            float e1 = exps(acc[nt][1], m2a);
            float e2 = exps(acc[nt][2], m2b);
            float e3 = exps(acc[nt][3], m2b);
            z0 += e0 + e1; z1 += e2 + e3;
            uint32_t h0 = pack_bf16(e0, e1);
            uint32_t h1 = pack_bf16(e2, e3);
            PH[nt][0] = h0; PH[nt][1] = h1;
            PL[nt][0] = pack_bf16(e0 - lowbf(h0), e1 - highbf(h0));
            PL[nt][1] = pack_bf16(e2 - lowbf(h1), e3 - highbf(h1));
            const int sg = s0 + scol + nt * 8;
            g_p16[pbase + ((size_t)qr << 9) + (sg >> 1)]       = pack_f16(e0, e1);
            g_p16[pbase + ((size_t)(qr + 8) << 9) + (sg >> 1)] = pack_f16(e2, e3);
        }

        // ---- PV: B via ldmatrix.trans on the SAME K tiles (V == K) ----
        #pragma unroll
        for (int dt = 0; dt < 4; ++dt) {
            const uint32_t dcol = 2 * (pv_dbase + dt * 16);
            #pragma unroll
            for (int kk = 0; kk < 2; ++kk) {
                const uint32_t srow = pv_srow0 + kk * 16;
                uint32_t av = sb + kb + srow * 128 + (dcol ^ ((uint32_t)tr << 4));
                uint32_t vh[4], vl[4];
                LDM4T(vh, av);
                LDM4T(vl, av + 16384);
                uint32_t aH[4] = {PH[2*kk][0], PH[2*kk][1], PH[2*kk+1][0], PH[2*kk+1][1]};
                uint32_t aL[4] = {PL[2*kk][0], PL[2*kk][1], PL[2*kk+1][0], PL[2*kk+1][1]};
                MMA(Dacc[2 * dt],     aH, vh[0], vh[1]);
                MMA(Dacc[2 * dt + 1], aH, vh[2], vh[3]);
                MMA(Dacc[2 * dt],     aL, vh[0], vh[1]);
                MMA(Dacc[2 * dt + 1], aL, vh[2], vh[3]);
                MMA(Dacc[2 * dt],     aH, vl[0], vl[1]);
                MMA(Dacc[2 * dt + 1], aH, vl[2], vl[3]);
            }
        }

        if (c == 7) {
            // ---- head end: Z reduce (4 s-quarters per row) ----
            z0 += __shfl_xor_sync(0xffffffffu, z0, 1);
            z0 += __shfl_xor_sync(0xffffffffu, z0, 2);
            z1 += __shfl_xor_sync(0xffffffffu, z1, 1);
            z1 += __shfl_xor_sync(0xffffffffu, z1, 2);
            if ((lane & 3) == 0) {
                ZS[(qw * 16 + (lane >> 2)) * 4 + sw]     = z0;
                ZS[(qw * 16 + (lane >> 2) + 8) * 4 + sw] = z1;
            }
            __syncthreads();   // [F] Z in; all tile reads of pair1 done
            if (tid < 64) {
                float v = 1.0f / (ZS[4 * tid] + ZS[4 * tid + 1]
                                + ZS[4 * tid + 2] + ZS[4 * tid + 3]);
                ZI[tid] = v;
                g_invZ[(h * 128 + cta) * 64 + tid] = v;
            }

            // sw=1,2,3 publish D partials (pair1 + Q region free; prefetch -> pair0)
            if (sw != 0) {
                float* P = (sw == 1) ? P1 : (sw == 2) ? P2 : P3;
                #pragma unroll
                for (int nt = 0; nt < 8; ++nt) {
                    int col = nt * 8 + tig2;
                    *(float2*)(P + qw * 1024 + (lane >> 2) * 64 + col) =
                        make_float2(Dacc[nt][0], Dacc[nt][1]);
                    *(float2*)(P + qw * 1024 + ((lane >> 2) + 8) * 64 + col) =
                        make_float2(Dacc[nt][2], Dacc[nt][3]);
                }
            }
            __syncthreads();   // [G]

            if (sw == 0) {     // reduce 4 partials + normalize + store O
                const float iza = ZI[qw * 16 + (lane >> 2)];
                const float izb = ZI[qw * 16 + (lane >> 2) + 8];
                float* orow0 = out + ((size_t)(n * L_S + q0 + qw * 16 + (lane >> 2))) * DM + h * D;
                float* orow1 = orow0 + (size_t)8 * DM;
                #pragma unroll
                for (int nt = 0; nt < 8; ++nt) {
                    int col = nt * 8 + tig2;
                    int o0 = qw * 1024 + (lane >> 2) * 64 + col;
                    int o1 = qw * 1024 + ((lane >> 2) + 8) * 64 + col;
                    float2 a1 = *(float2*)(P1 + o0), b1 = *(float2*)(P1 + o1);
                    float2 a2 = *(float2*)(P2 + o0), b2 = *(float2*)(P2 + o1);
                    float2 a3 = *(float2*)(P3 + o0), b3 = *(float2*)(P3 + o1);
                    *(float2*)(orow0 + col) = make_float2(
                        (Dacc[nt][0] + a1.x + a2.x + a3.x) * iza,
                        (Dacc[nt][1] + a1.y + a2.y + a3.y) * iza);
                    *(float2*)(orow1 + col) = make_float2(
                        (Dacc[nt][2] + b1.x + b2.x + b3.x) * izb,
                        (Dacc[nt][3] + b1.y + b2.y + b3.y) * izb);
                }
            }
        }
    }
}

extern "C" void kernel_launch(void* const* d_in, const int* in_sizes, int n_in,
                              void* d_out, int out_size) {
    const float* in = (const float*)d_in[0];
    float* out = (float*)d_out;
    const size_t out_elems  = (size_t)N_B * L_S * DM;   // 8,388,608
    const size_t attn_elems = (size_t)N_B * L_S * L_S;  // 8,388,608
    int write_attn = (out_size >= (int)(out_elems + attn_elems)) ? 1 : 0;
    float* attn = out + out_elems;

    cudaFuncSetAttribute(attn_mma_kernel,
                         cudaFuncAttributeMaxDynamicSharedMemorySize, SMEM_SZ);

    prep_kernel<<<4096, 512>>>(in);                     // split to tile images
    dim3 grid(16, 8);                                   // 128 CTAs, 512 threads
    attn_mma_kernel<<<grid, THREADS, SMEM_SZ>>>(out);
    if (write_attn)
        merge_kernel<<<16384, 256>>>(attn);             // attn head-mean
}

// round 11
// speedup vs baseline: 4.7108x; 1.1511x over previous
#include <cuda_runtime.h>
#include <cuda_fp16.h>
#include <stdint.h>
#include <math.h>

#define N_B 8
#define L_S 1024
#define DM  1024
#define H   16
#define D   64
#define QB  64
#define CH  128
#define THREADS 512
// fold 1/sqrt(64) into exp: exp(0.125*S - m) = ex2(S*EXP_C - m2)
#define EXP_C 0.18033688011112042f
#define LOG2E 1.4426950408889634f

// SMEM byte offsets
#define SO_KH0 0          // pair0 hi (16KB); lo at +16384
#define SO_KH1 32768      // pair1 hi; lo at +16384
#define SO_QH  65536      // Q hi (8KB)
#define SO_ESM 73728      // e-stage: 64 rows x 272B (17408B); head-end: P3
#define SO_ZS  91136      // 64 x 4 f32 Z partials (1KB)
#define SO_ZI  92160      // 64 f32 invZ (256B)
#define SMEM_SZ 92416

// pre-split fp16 hi/lo tile images (exact smem byte layout), 16KB per (n,h,c)
__device__ char     g_hi[(size_t)16 << 20];                  // 16MB
__device__ char     g_lo[(size_t)16 << 20];                  // 16MB
__device__ uint32_t g_p16[(size_t)16 * 128 * 64 * 512];      // 256MB fp16x2 e-planes
__device__ float    g_invZ[16 * 128 * 64];                   // 512KB

// ---------------- helpers ----------------
__device__ __forceinline__ uint32_t s2u(const void* p) {
    uint32_t a;
    asm("{ .reg .u64 t; cvta.to.shared.u64 t, %1; cvt.u32.u64 %0, t; }" : "=r"(a) : "l"(p));
    return a;
}
__device__ __forceinline__ uint32_t pack_f16(float lo, float hi) {    // lo -> bits[15:0]
    uint32_t r;
    asm("cvt.rn.f16x2.f32 %0, %1, %2;" : "=r"(r) : "f"(hi), "f"(lo));
    return r;
}
__device__ __forceinline__ float2 unpack_f16(uint32_t w) {
    __half2 h = *reinterpret_cast<__half2*>(&w);
    return __half22float2(h);
}
__device__ __forceinline__ float exps(float x, float m2) {   // exp(0.125*x) * 2^-m2
    float r, t = fmaf(x, EXP_C, -m2);
    asm("ex2.approx.ftz.f32 %0, %1;" : "=f"(r) : "f"(t));
    return r;
}

#define LDM4(r, ad) \
    asm volatile("ldmatrix.sync.aligned.m8n8.x4.shared.b16 {%0,%1,%2,%3}, [%4];" \
        : "=r"((r)[0]), "=r"((r)[1]), "=r"((r)[2]), "=r"((r)[3]) : "r"(ad))

#define LDM4T(r, ad) \
    asm volatile("ldmatrix.sync.aligned.m8n8.x4.trans.shared.b16 {%0,%1,%2,%3}, [%4];" \
        : "=r"((r)[0]), "=r"((r)[1]), "=r"((r)[2]), "=r"((r)[3]) : "r"(ad))

#define MMA(c, a, b0_, b1_) \
    asm volatile("mma.sync.aligned.m16n8k16.row.col.f32.f16.f16.f32 " \
        "{%0,%1,%2,%3}, {%4,%5,%6,%7}, {%8,%9}, {%0,%1,%2,%3};" \
        : "+f"((c)[0]), "+f"((c)[1]), "+f"((c)[2]), "+f"((c)[3]) \
        : "r"((a)[0]), "r"((a)[1]), "r"((a)[2]), "r"((a)[3]), "r"(b0_), "r"(b1_))

#define CPA16(sa, g) \
    asm volatile("cp.async.cg.shared.global [%0], [%1], 16;" :: "r"(sa), "l"(g))
#define CPA_COMMIT() asm volatile("cp.async.commit_group;" ::: "memory")
#define CPA_WAIT0()  asm volatile("cp.async.wait_group 0;" ::: "memory")
#define CPA_WAIT1()  asm volatile("cp.async.wait_group 1;" ::: "memory")

__device__ __forceinline__ void cvt_split16(float4 v, uint32_t& h0, uint32_t& h1,
                                            uint32_t& l0, uint32_t& l1) {
    h0 = pack_f16(v.x, v.y);
    h1 = pack_f16(v.z, v.w);
    float2 a = unpack_f16(h0), b = unpack_f16(h1);
    l0 = pack_f16(v.x - a.x, v.y - a.y);
    l1 = pack_f16(v.z - b.x, v.w - b.y);
}

// ---------------- preprocess: f32 -> fp16 hi/lo tile images ----------------
extern "C" __global__ void __launch_bounds__(512)
prep_kernel(const float* __restrict__ in)
{
    int idx = blockIdx.x * 512 + threadIdx.x;     // 2M threads, 1 float4 each
    int dqi = idx & 255;                          // h*16 + dq
    int s   = (idx >> 8) & 1023;
    int n   = idx >> 18;
    int dq = dqi & 15;
    float4 v = *(const float4*)(in + (((size_t)(n * 1024 + s)) << 10) + dqi * 4);
    uint32_t h0, h1, l0, l1; cvt_split16(v, h0, h1, l0, l1);
    uint32_t t = (uint32_t)((n * 16 + (dqi >> 4)) * 8 + (s >> 7));
    uint32_t b = (uint32_t)((s & 127) * 128 + ((dq * 8) ^ ((s & 7) << 4)));
    *(uint2*)(g_hi + (((size_t)t) << 14) + b) = make_uint2(h0, h1);
    *(uint2*)(g_lo + (((size_t)t) << 14) + b) = make_uint2(l0, l1);
}

// ---------------- merge: attn = (1/16) sum_h e'_h * invZ'_h ----------------
extern "C" __global__ void __launch_bounds__(256)
merge_kernel(float* __restrict__ attn)
{
    int idx = blockIdx.x * 256 + threadIdx.x;     // 4.19M threads, 2 s each
    int s2 = idx & 511;
    int qg = (idx >> 9) & 1023;
    int n  = idx >> 19;
    int cta = n * 16 + (qg >> 6);
    int ql  = qg & 63;
    float ax = 0.f, ay = 0.f;
    #pragma unroll
    for (int h = 0; h < 16; ++h) {
        int base = (h * 128 + cta) * 64 + ql;
        uint32_t w = g_p16[(((size_t)base) << 9) + s2];
        float iz = g_invZ[base];
        float2 v = unpack_f16(w);
        ax += v.x * iz; ay += v.y * iz;
    }
    ((float2*)attn)[idx] = make_float2(ax * (1.f / 16.f), ay * (1.f / 16.f));
}

// ---------------- main attention kernel ----------------
extern "C" __global__ void __launch_bounds__(THREADS)
attn_mma_kernel(float* __restrict__ out)
{
    extern __shared__ __align__(1024) char smem[];
    const uint32_t sb = s2u(smem);
    float* ZS = (float*)(smem + SO_ZS);
    float* ZI = (float*)(smem + SO_ZI);
    float* P1 = (float*)(smem + SO_KH1);          // head-end D-partials
    float* P2 = (float*)(smem + SO_KH1 + 16384);
    float* P3 = (float*)(smem + SO_ESM);

    const int tid  = threadIdx.x;
    const int lane = tid & 31;
    const int warp = tid >> 5;        // 16 warps
    const int qw   = warp & 3;        // q-tile group (16 rows)
    const int sw   = warp >> 2;       // s-quarter (32 cols)
    const int qb   = blockIdx.x, n = blockIdx.y;
    const int q0   = qb * QB;
    const int cta  = n * 16 + qb;

    const int qr   = qw * 16 + (lane >> 2);   // C/A-frag row (q)
    const int tig2 = 2 * (lane & 3);          // col pair base

    // trans-ldmatrix lane geometry for PV B-operand
    const int tg = lane >> 3, tr = lane & 7;
    const uint32_t pv_srow0 = (uint32_t)(sw * 32 + (tg & 1) * 8 + tr);
    const uint32_t pv_dbase = (uint32_t)((tg >> 1) * 8);

    // e-stage copy geometry: thread owns 32B of the logical 16KB chunk image
    const int cq  = tid >> 3;             // q row 0..63
    const int coff = (tid & 7) * 32;      // byte offset in 256B row

    // prologue: prefetch chunk (h=0,c=0) tile pair into pair0
    {
        const size_t tb = ((size_t)(n * 16 * 8)) << 14;     // tile (n,0,0)
        #pragma unroll
        for (int k = 0; k < 2; ++k) {
            uint32_t o = (uint32_t)(k * 512 + tid) * 16;
            CPA16(sb + SO_KH0 + o,         g_hi + tb + o);
            CPA16(sb + SO_KH0 + 16384 + o, g_lo + tb + o);
        }
        CPA_COMMIT();
    }

    uint32_t QHf[4][4];
    float Dacc[8][4];
    float z0 = 0.f, z1 = 0.f;
    float m2a = 0.f, m2b = 0.f;       // per-row exp shift (log2 units)
    size_t pbase = 0;

    for (int i = 0; i < H * 8; ++i) {
        const int h = i >> 3, c = i & 7;
        const uint32_t kb = (i & 1) ? SO_KH1 : SO_KH0;

        CPA_WAIT0();
        __syncthreads();   // [A] cur tiles resident; ESM/P-buffers free

        if (c == 0) {
            // ---- Q hi tile image (8KB), own cp.async group ----
            const size_t tq = ((size_t)((n * 16 + h) * 8 + (qb >> 1))) << 14;
            const size_t qoff = (size_t)(qb & 1) * 8192;
            CPA16(sb + SO_QH + (uint32_t)tid * 16, g_hi + tq + qoff + tid * 16);
            CPA_COMMIT();
        }

        // ---- prefetch chunk i+1 into the other pair ----
        if (i + 1 < H * 8) {
            const uint32_t dkb = ((i + 1) & 1) ? SO_KH1 : SO_KH0;
            const size_t tt = ((size_t)((n * 16 + ((i + 1) >> 3)) * 8 + ((i + 1) & 7))) << 14;
            #pragma unroll
            for (int k = 0; k < 2; ++k) {
                uint32_t o = (uint32_t)(k * 512 + tid) * 16;
                CPA16(sb + dkb + o,         g_hi + tt + o);
                CPA16(sb + dkb + 16384 + o, g_lo + tt + o);
            }
            CPA_COMMIT();
        }

        if (c == 0) {
            CPA_WAIT1();       // Q group (older) done; chunk prefetch may fly
            __syncthreads();
            // ---- persistent Q hi fragments ----
            const uint32_t row = qw * 16 + (lane & 15);
            const uint32_t swz = (row & 7) << 4;
            #pragma unroll
            for (int kk = 0; kk < 4; ++kk) {
                uint32_t col = kk * 32 + ((lane >> 4) << 4);
                LDM4(QHf[kk], sb + SO_QH + row * 128 + (col ^ swz));
            }
            // ---- per-row shift: m2 ~= 0.125*|q_row|^2 * log2(e) (hi parts) ----
            {
                float sa = 0.f, sbq = 0.f;
                const int r0 = qr, r1 = qr + 8;
                #pragma unroll
                for (int t = 0; t < 4; ++t) {
                    int dq = (lane & 3) * 4 + t;     // 8B group index 0..15
                    uint32_t b0 = r0 * 128 + ((dq * 8) ^ ((r0 & 7) << 4));
                    uint32_t b1 = r1 * 128 + ((dq * 8) ^ ((r1 & 7) << 4));
                    uint2 w0 = *(uint2*)(smem + SO_QH + b0);
                    uint2 w1 = *(uint2*)(smem + SO_QH + b1);
                    float2 a0 = unpack_f16(w0.x), a1 = unpack_f16(w0.y);
                    float2 c0 = unpack_f16(w1.x), c1 = unpack_f16(w1.y);
                    sa  += a0.x*a0.x + a0.y*a0.y + a1.x*a1.x + a1.y*a1.y;
                    sbq += c0.x*c0.x + c0.y*c0.y + c1.x*c1.x + c1.y*c1.y;
                }
                sa  += __shfl_xor_sync(0xffffffffu, sa, 1);
                sa  += __shfl_xor_sync(0xffffffffu, sa, 2);
                sbq += __shfl_xor_sync(0xffffffffu, sbq, 1);
                sbq += __shfl_xor_sync(0xffffffffu, sbq, 2);
                m2a = sa  * (0.125f * LOG2E);
                m2b = sbq * (0.125f * LOG2E);
            }
            #pragma unroll
            for (int x = 0; x < 8; ++x)
                #pragma unroll
                for (int j = 0; j < 4; ++j) Dacc[x][j] = 0.f;
            z0 = 0.f; z1 = 0.f;
            pbase = ((size_t)(h * 128 + cta)) << 15;
        }

        // ---- QK^T: 2-pass fp16 split (Qhi*Khi + Qhi*Klo) ----
        float acc[4][4];
        #pragma unroll
        for (int x = 0; x < 4; ++x)
            #pragma unroll
            for (int j = 0; j < 4; ++j) acc[x][j] = 0.f;

        #pragma unroll
        for (int np = 0; np < 2; ++np) {
            const uint32_t rowb = sw * 32 + np * 16 + (lane & 7) + ((lane >> 4) << 3);
            const uint32_t rsw = (rowb & 7) << 4;
            #pragma unroll
            for (int kk = 0; kk < 4; ++kk) {
                uint32_t col = kk * 32 + ((lane >> 3) & 1) * 16;
                uint32_t ah = sb + kb + rowb * 128 + (col ^ rsw);
                uint32_t bh[4], bl[4];
                LDM4(bh, ah);
                LDM4(bl, ah + 16384);
                MMA(acc[2 * np],     QHf[kk], bh[0], bh[1]);
                MMA(acc[2 * np + 1], QHf[kk], bh[2], bh[3]);
                MMA(acc[2 * np],     QHf[kk], bl[0], bl[1]);
                MMA(acc[2 * np + 1], QHf[kk], bl[2], bl[3]);
            }
        }

        // ---- shifted exp, Z accumulate, P hi/lo pack, e' -> ESM ----
        uint32_t PH[4][2], PL[4][2];
        #pragma unroll
        for (int nt = 0; nt < 4; ++nt) {
            float e0 = exps(acc[nt][0], m2a);
            float e1 = exps(acc[nt][1], m2a);
            float e2 = exps(acc[nt][2], m2b);
            float e3 = exps(acc[nt][3], m2b);
            z0 += e0 + e1; z1 += e2 + e3;
            uint32_t h0 = pack_f16(e0, e1);
            uint32_t h1 = pack_f16(e2, e3);
            PH[nt][0] = h0; PH[nt][1] = h1;
            float2 f0 = unpack_f16(h0), f1 = unpack_f16(h1);
            PL[nt][0] = pack_f16(e0 - f0.x, e1 - f0.y);
            PL[nt][1] = pack_f16(e2 - f1.x, e3 - f1.y);
            uint32_t eb = sw * 64 + nt * 16 + (lane & 3) * 4;
            *(uint32_t*)(smem + SO_ESM + qr * 272 + eb)       = h0;
            *(uint32_t*)(smem + SO_ESM + (qr + 8) * 272 + eb) = h1;
        }
        __syncthreads();   // [E] ESM chunk image complete

        // ---- cooperative coalesced e-plane store (16KB -> g_p16) ----
        {
            const char* src = smem + SO_ESM + cq * 272 + coff;
            uint4 v0 = *(const uint4*)(src);
            uint4 v1 = *(const uint4*)(src + 16);
            uint32_t* dst = g_p16 + pbase + cq * 512 + c * 64 + (coff >> 2);
            *(uint4*)(dst)     = v0;
            *(uint4*)(dst + 4) = v1;
        }

        // ---- PV: 3-pass (Phi*Vhi + Plo*Vhi + Phi*Vlo), V == K tiles ----
        #pragma unroll
        for (int dt = 0; dt < 4; ++dt) {
            const uint32_t dcol = 2 * (pv_dbase + dt * 16);
            #pragma unroll
            for (int kk = 0; kk < 2; ++kk) {
                const uint32_t srow = pv_srow0 + kk * 16;
                uint32_t av = sb + kb + srow * 128 + (dcol ^ ((uint32_t)tr << 4));
                uint32_t vh[4], vl[4];
                LDM4T(vh, av);
                LDM4T(vl, av + 16384);
                uint32_t aH[4] = {PH[2*kk][0], PH[2*kk][1], PH[2*kk+1][0], PH[2*kk+1][1]};
                uint32_t aL[4] = {PL[2*kk][0], PL[2*kk][1], PL[2*kk+1][0], PL[2*kk+1][1]};
                MMA(Dacc[2 * dt],     aH, vh[0], vh[1]);
                MMA(Dacc[2 * dt + 1], aH, vh[2], vh[3]);
                MMA(Dacc[2 * dt],     aL, vh[0], vh[1]);
                MMA(Dacc[2 * dt + 1], aL, vh[2], vh[3]);
                MMA(Dacc[2 * dt],     aH, vl[0], vl[1]);
                MMA(Dacc[2 * dt + 1], aH, vl[2], vl[3]);
            }
        }

        if (c == 7) {
            // ---- head end: Z reduce (4 s-quarters per row) ----
            z0 += __shfl_xor_sync(0xffffffffu, z0, 1);
            z0 += __shfl_xor_sync(0xffffffffu, z0, 2);
            z1 += __shfl_xor_sync(0xffffffffu, z1, 1);
            z1 += __shfl_xor_sync(0xffffffffu, z1, 2);
            if ((lane & 3) == 0) {
                ZS[(qw * 16 + (lane >> 2)) * 4 + sw]     = z0;
                ZS[(qw * 16 + (lane >> 2) + 8) * 4 + sw] = z1;
            }
            __syncthreads();   // [F] Z in; tile reads + ESM reads done
            if (tid < 64) {
                float v = 1.0f / (ZS[4 * tid] + ZS[4 * tid + 1]
                                + ZS[4 * tid + 2] + ZS[4 * tid + 3]);
                ZI[tid] = v;
                g_invZ[(h * 128 + cta) * 64 + tid] = v;
            }

            // sw=1,2,3 publish D partials (pair1 + ESM free; prefetch -> pair0)
            if (sw != 0) {
                float* P = (sw == 1) ? P1 : (sw == 2) ? P2 : P3;
                #pragma unroll
                for (int nt = 0; nt < 8; ++nt) {
                    int col = nt * 8 + tig2;
                    *(float2*)(P + qw * 1024 + (lane >> 2) * 64 + col) =
                        make_float2(Dacc[nt][0], Dacc[nt][1]);
                    *(float2*)(P + qw * 1024 + ((lane >> 2) + 8) * 64 + col) =
                        make_float2(Dacc[nt][2], Dacc[nt][3]);
                }
            }
            __syncthreads();   // [G]

            if (sw == 0) {     // reduce 4 partials + normalize + store O
                const float iza = ZI[qw * 16 + (lane >> 2)];
                const float izb = ZI[qw * 16 + (lane >> 2) + 8];
                float* orow0 = out + ((size_t)(n * L_S + q0 + qw * 16 + (lane >> 2))) * DM + h * D;
                float* orow1 = orow0 + (size_t)8 * DM;
                #pragma unroll
                for (int nt = 0; nt < 8; ++nt) {
                    int col = nt * 8 + tig2;
                    int o0 = qw * 1024 + (lane >> 2) * 64 + col;
                    int o1 = qw * 1024 + ((lane >> 2) + 8) * 64 + col;
                    float2 a1 = *(float2*)(P1 + o0), b1 = *(float2*)(P1 + o1);
                    float2 a2 = *(float2*)(P2 + o0), b2 = *(float2*)(P2 + o1);
                    float2 a3 = *(float2*)(P3 + o0), b3 = *(float2*)(P3 + o1);
                    *(float2*)(orow0 + col) = make_float2(
                        (Dacc[nt][0] + a1.x + a2.x + a3.x) * iza,
                        (Dacc[nt][1] + a1.y + a2.y + a3.y) * iza);
                    *(float2*)(orow1 + col) = make_float2(
                        (Dacc[nt][2] + b1.x + b2.x + b3.x) * izb,
                        (Dacc[nt][3] + b1.y + b2.y + b3.y) * izb);
                }
            }
        }
    }
}

extern "C" void kernel_launch(void* const* d_in, const int* in_sizes, int n_in,
                              void* d_out, int out_size) {
    const float* in = (const float*)d_in[0];
    float* out = (float*)d_out;
    const size_t out_elems  = (size_t)N_B * L_S * DM;   // 8,388,608
    const size_t attn_elems = (size_t)N_B * L_S * L_S;  // 8,388,608
    int write_attn = (out_size >= (int)(out_elems + attn_elems)) ? 1 : 0;
    float* attn = out + out_elems;

    cudaFuncSetAttribute(attn_mma_kernel,
                         cudaFuncAttributeMaxDynamicSharedMemorySize, SMEM_SZ);

    prep_kernel<<<4096, 512>>>(in);                     // split to tile images
    dim3 grid(16, 8);                                   // 128 CTAs, 512 threads
    attn_mma_kernel<<<grid, THREADS, SMEM_SZ>>>(out);
    if (write_attn)
        merge_kernel<<<16384, 256>>>(attn);             // attn head-mean
}

// round 12
// speedup vs baseline: 5.1207x; 1.0870x over previous
#include <cuda_runtime.h>
#include <cuda_fp16.h>
#include <stdint.h>
#include <math.h>

#define N_B 8
#define L_S 1024
#define DM  1024
#define H   16
#define D   64
#define QB  64
#define CH  128
#define THREADS 512
// fold 1/sqrt(64) into exp: exp(0.125*S - m) = ex2(S*EXP_C - m2)
#define EXP_C 0.18033688011112042f
#define LOG2E 1.4426950408889634f

// SMEM byte offsets
#define SO_KH0 0          // pair0 hi (16KB); lo at +16384
#define SO_KH1 32768      // pair1 hi; lo at +16384
#define SO_QH  65536      // Q hi (8KB)
#define SO_ESM 73728      // e-stage: 64 rows x 272B (17408B); head-end: P3
#define SO_ZS  91136      // 64 x 4 f32 Z partials (1KB)
#define SO_ZI  92160      // 64 f32 invZ (256B)
#define SMEM_SZ 92416

// pre-split fp16 hi/lo tile images (exact smem byte layout), 16KB per (n,h,c)
__device__ char     g_hi[(size_t)16 << 20];                  // 16MB
__device__ char     g_lo[(size_t)16 << 20];                  // 16MB
__device__ uint32_t g_p16[(size_t)16 * 128 * 64 * 512];      // 256MB fp16x2 e-planes
__device__ float    g_invZ[16 * 128 * 64];                   // 512KB

// ---------------- helpers ----------------
__device__ __forceinline__ uint32_t s2u(const void* p) {
    uint32_t a;
    asm("{ .reg .u64 t; cvta.to.shared.u64 t, %1; cvt.u32.u64 %0, t; }" : "=r"(a) : "l"(p));
    return a;
}
__device__ __forceinline__ uint32_t pack_f16(float lo, float hi) {    // lo -> bits[15:0]
    uint32_t r;
    asm("cvt.rn.f16x2.f32 %0, %1, %2;" : "=r"(r) : "f"(hi), "f"(lo));
    return r;
}
__device__ __forceinline__ float2 unpack_f16(uint32_t w) {
    __half2 h = *reinterpret_cast<__half2*>(&w);
    return __half22float2(h);
}
__device__ __forceinline__ float exps(float x, float m2) {   // exp(0.125*x) * 2^-m2
    float r, t = fmaf(x, EXP_C, -m2);
    asm("ex2.approx.ftz.f32 %0, %1;" : "=f"(r) : "f"(t));
    return r;
}

#define LDM4(r, ad) \
    asm volatile("ldmatrix.sync.aligned.m8n8.x4.shared.b16 {%0,%1,%2,%3}, [%4];" \
        : "=r"((r)[0]), "=r"((r)[1]), "=r"((r)[2]), "=r"((r)[3]) : "r"(ad))

#define LDM4T(r, ad) \
    asm volatile("ldmatrix.sync.aligned.m8n8.x4.trans.shared.b16 {%0,%1,%2,%3}, [%4];" \
        : "=r"((r)[0]), "=r"((r)[1]), "=r"((r)[2]), "=r"((r)[3]) : "r"(ad))

#define MMA(c, a, b0_, b1_) \
    asm volatile("mma.sync.aligned.m16n8k16.row.col.f32.f16.f16.f32 " \
        "{%0,%1,%2,%3}, {%4,%5,%6,%7}, {%8,%9}, {%0,%1,%2,%3};" \
        : "+f"((c)[0]), "+f"((c)[1]), "+f"((c)[2]), "+f"((c)[3]) \
        : "r"((a)[0]), "r"((a)[1]), "r"((a)[2]), "r"((a)[3]), "r"(b0_), "r"(b1_))

#define CPA16(sa, g) \
    asm volatile("cp.async.cg.shared.global [%0], [%1], 16;" :: "r"(sa), "l"(g))
#define CPA_COMMIT() asm volatile("cp.async.commit_group;" ::: "memory")
#define CPA_WAIT0()  asm volatile("cp.async.wait_group 0;" ::: "memory")
#define CPA_WAIT1()  asm volatile("cp.async.wait_group 1;" ::: "memory")

__device__ __forceinline__ void cvt_split16(float4 v, uint32_t& h0, uint32_t& h1,
                                            uint32_t& l0, uint32_t& l1) {
    h0 = pack_f16(v.x, v.y);
    h1 = pack_f16(v.z, v.w);
    float2 a = unpack_f16(h0), b = unpack_f16(h1);
    l0 = pack_f16(v.x - a.x, v.y - a.y);
    l1 = pack_f16(v.z - b.x, v.w - b.y);
}

// ---------------- preprocess: f32 -> fp16 hi/lo tile images ----------------
extern "C" __global__ void __launch_bounds__(512)
prep_kernel(const float* __restrict__ in)
{
    int idx = blockIdx.x * 512 + threadIdx.x;     // 2M threads, 1 float4 each
    int dqi = idx & 255;                          // h*16 + dq
    int s   = (idx >> 8) & 1023;
    int n   = idx >> 18;
    int dq = dqi & 15;
    float4 v = *(const float4*)(in + (((size_t)(n * 1024 + s)) << 10) + dqi * 4);
    uint32_t h0, h1, l0, l1; cvt_split16(v, h0, h1, l0, l1);
    uint32_t t = (uint32_t)((n * 16 + (dqi >> 4)) * 8 + (s >> 7));
    uint32_t b = (uint32_t)((s & 127) * 128 + ((dq * 8) ^ ((s & 7) << 4)));
    *(uint2*)(g_hi + (((size_t)t) << 14) + b) = make_uint2(h0, h1);
    *(uint2*)(g_lo + (((size_t)t) << 14) + b) = make_uint2(l0, l1);
}

// ---------------- merge: attn = (1/16) sum_h e'_h * invZ'_h ----------------
extern "C" __global__ void __launch_bounds__(256)
merge_kernel(float* __restrict__ attn)
{
    int idx = blockIdx.x * 256 + threadIdx.x;     // 4.19M threads, 2 s each
    int s2 = idx & 511;
    int qg = (idx >> 9) & 1023;
    int n  = idx >> 19;
    int cta = n * 16 + (qg >> 6);
    int ql  = qg & 63;
    float ax = 0.f, ay = 0.f;
    #pragma unroll
    for (int h = 0; h < 16; ++h) {
        int base = (h * 128 + cta) * 64 + ql;
        uint32_t w = g_p16[(((size_t)base) << 9) + s2];
        float iz = g_invZ[base];
        float2 v = unpack_f16(w);
        ax += v.x * iz; ay += v.y * iz;
    }
    ((float2*)attn)[idx] = make_float2(ax * (1.f / 16.f), ay * (1.f / 16.f));
}

// ---------------- main attention kernel ----------------
extern "C" __global__ void __launch_bounds__(THREADS)
attn_mma_kernel(float* __restrict__ out)
{
    extern __shared__ __align__(1024) char smem[];
    const uint32_t sb = s2u(smem);
    float* ZS = (float*)(smem + SO_ZS);
    float* ZI = (float*)(smem + SO_ZI);
    float* P1 = (float*)(smem + SO_KH1);          // head-end D-partials
    float* P2 = (float*)(smem + SO_KH1 + 16384);
    float* P3 = (float*)(smem + SO_ESM);

    const int tid  = threadIdx.x;
    const int lane = tid & 31;
    const int warp = tid >> 5;        // 16 warps
    const int qw   = warp & 3;        // q-tile group (16 rows)
    const int sw   = warp >> 2;       // s-quarter (32 cols)
    const int qb   = blockIdx.x, n = blockIdx.y;
    const int q0   = qb * QB;
    const int cta  = n * 16 + qb;

    const int qr   = qw * 16 + (lane >> 2);   // C/A-frag row (q)
    const int tig2 = 2 * (lane & 3);          // col pair base

    // trans-ldmatrix lane geometry for PV B-operand
    const int tg = lane >> 3, tr = lane & 7;
    const uint32_t pv_srow0 = (uint32_t)(sw * 32 + (tg & 1) * 8 + tr);
    const uint32_t pv_dbase = (uint32_t)((tg >> 1) * 8);

    // e-stage copy geometry: thread owns 32B of the logical 16KB chunk image
    const int cq  = tid >> 3;             // q row 0..63
    const int coff = (tid & 7) * 32;      // byte offset in 256B row

    // prologue: prefetch chunk (h=0,c=0) tile pair into pair0
    {
        const size_t tb = ((size_t)(n * 16 * 8)) << 14;     // tile (n,0,0)
        #pragma unroll
        for (int k = 0; k < 2; ++k) {
            uint32_t o = (uint32_t)(k * 512 + tid) * 16;
            CPA16(sb + SO_KH0 + o,         g_hi + tb + o);
            CPA16(sb + SO_KH0 + 16384 + o, g_lo + tb + o);
        }
        CPA_COMMIT();
    }

    uint32_t QHf[4][4];
    float Dacc[8][4];
    float z0 = 0.f, z1 = 0.f;
    float m2a = 0.f, m2b = 0.f;       // per-row exp shift (log2 units)
    size_t pbase = 0;

    for (int i = 0; i < H * 8; ++i) {
        const int h = i >> 3, c = i & 7;
        const uint32_t kb = (i & 1) ? SO_KH1 : SO_KH0;

        CPA_WAIT0();
        __syncthreads();   // [A] cur tiles resident; ESM/P-buffers free

        if (c == 0) {
            // ---- Q hi tile image (8KB), own cp.async group ----
            const size_t tq = ((size_t)((n * 16 + h) * 8 + (qb >> 1))) << 14;
            const size_t qoff = (size_t)(qb & 1) * 8192;
            CPA16(sb + SO_QH + (uint32_t)tid * 16, g_hi + tq + qoff + tid * 16);
            CPA_COMMIT();
        }

        // ---- prefetch chunk i+1 into the other pair ----
        if (i + 1 < H * 8) {
            const uint32_t dkb = ((i + 1) & 1) ? SO_KH1 : SO_KH0;
            const size_t tt = ((size_t)((n * 16 + ((i + 1) >> 3)) * 8 + ((i + 1) & 7))) << 14;
            #pragma unroll
            for (int k = 0; k < 2; ++k) {
                uint32_t o = (uint32_t)(k * 512 + tid) * 16;
                CPA16(sb + dkb + o,         g_hi + tt + o);
                CPA16(sb + dkb + 16384 + o, g_lo + tt + o);
            }
            CPA_COMMIT();
        }

        if (c == 0) {
            CPA_WAIT1();       // Q group (older) done; chunk prefetch may fly
            __syncthreads();
            // ---- persistent Q hi fragments ----
            const uint32_t row = qw * 16 + (lane & 15);
            const uint32_t swz = (row & 7) << 4;
            #pragma unroll
            for (int kk = 0; kk < 4; ++kk) {
                uint32_t col = kk * 32 + ((lane >> 4) << 4);
                LDM4(QHf[kk], sb + SO_QH + row * 128 + (col ^ swz));
            }
            // ---- per-row shift: m2 ~= 0.125*|q_row|^2 * log2(e) (hi parts) ----
            {
                float sa = 0.f, sbq = 0.f;
                const int r0 = qr, r1 = qr + 8;
                #pragma unroll
                for (int t = 0; t < 4; ++t) {
                    int dq = (lane & 3) * 4 + t;     // 8B group index 0..15
                    uint32_t b0 = r0 * 128 + ((dq * 8) ^ ((r0 & 7) << 4));
                    uint32_t b1 = r1 * 128 + ((dq * 8) ^ ((r1 & 7) << 4));
                    uint2 w0 = *(uint2*)(smem + SO_QH + b0);
                    uint2 w1 = *(uint2*)(smem + SO_QH + b1);
                    float2 a0 = unpack_f16(w0.x), a1 = unpack_f16(w0.y);
                    float2 c0 = unpack_f16(w1.x), c1 = unpack_f16(w1.y);
                    sa  += a0.x*a0.x + a0.y*a0.y + a1.x*a1.x + a1.y*a1.y;
                    sbq += c0.x*c0.x + c0.y*c0.y + c1.x*c1.x + c1.y*c1.y;
                }
                sa  += __shfl_xor_sync(0xffffffffu, sa, 1);
                sa  += __shfl_xor_sync(0xffffffffu, sa, 2);
                sbq += __shfl_xor_sync(0xffffffffu, sbq, 1);
                sbq += __shfl_xor_sync(0xffffffffu, sbq, 2);
                m2a = sa  * (0.125f * LOG2E);
                m2b = sbq * (0.125f * LOG2E);
            }
            #pragma unroll
            for (int x = 0; x < 8; ++x)
                #pragma unroll
                for (int j = 0; j < 4; ++j) Dacc[x][j] = 0.f;
            z0 = 0.f; z1 = 0.f;
            pbase = ((size_t)(h * 128 + cta)) << 15;
        }

        // ---- QK^T: 2-pass fp16 split (Qhi*Khi + Qhi*Klo) ----
        float acc[4][4];
        #pragma unroll
        for (int x = 0; x < 4; ++x)
            #pragma unroll
            for (int j = 0; j < 4; ++j) acc[x][j] = 0.f;

        #pragma unroll
        for (int np = 0; np < 2; ++np) {
            const uint32_t rowb = sw * 32 + np * 16 + (lane & 7) + ((lane >> 4) << 3);
            const uint32_t rsw = (rowb & 7) << 4;
            #pragma unroll
            for (int kk = 0; kk < 4; ++kk) {
                uint32_t col = kk * 32 + ((lane >> 3) & 1) * 16;
                uint32_t ah = sb + kb + rowb * 128 + (col ^ rsw);
                uint32_t bh[4], bl[4];
                LDM4(bh, ah);
                LDM4(bl, ah + 16384);
                MMA(acc[2 * np],     QHf[kk], bh[0], bh[1]);
                MMA(acc[2 * np + 1], QHf[kk], bh[2], bh[3]);
                MMA(acc[2 * np],     QHf[kk], bl[0], bl[1]);
                MMA(acc[2 * np + 1], QHf[kk], bl[2], bl[3]);
            }
        }

        // ---- shifted exp, Z accumulate, P hi/lo pack, e' -> ESM ----
        uint32_t PH[4][2], PL[4][2];
        #pragma unroll
        for (int nt = 0; nt < 4; ++nt) {
            float e0 = exps(acc[nt][0], m2a);
            float e1 = exps(acc[nt][1], m2a);
            float e2 = exps(acc[nt][2], m2b);
            float e3 = exps(acc[nt][3], m2b);
            z0 += e0 + e1; z1 += e2 + e3;
            uint32_t h0 = pack_f16(e0, e1);
            uint32_t h1 = pack_f16(e2, e3);
            PH[nt][0] = h0; PH[nt][1] = h1;
            float2 f0 = unpack_f16(h0), f1 = unpack_f16(h1);
            PL[nt][0] = pack_f16(e0 - f0.x, e1 - f0.y);
            PL[nt][1] = pack_f16(e2 - f1.x, e3 - f1.y);
            uint32_t eb = sw * 64 + nt * 16 + (lane & 3) * 4;
            *(uint32_t*)(smem + SO_ESM + qr * 272 + eb)       = h0;
            *(uint32_t*)(smem + SO_ESM + (qr + 8) * 272 + eb) = h1;
        }
        __syncthreads();   // [E] ESM chunk image complete

        // ---- cooperative coalesced e-plane store (16KB -> g_p16) ----
        {
            const char* src = smem + SO_ESM + cq * 272 + coff;
            uint4 v0 = *(const uint4*)(src);
            uint4 v1 = *(const uint4*)(src + 16);
            uint32_t* dst = g_p16 + pbase + cq * 512 + c * 64 + (coff >> 2);
            *(uint4*)(dst)     = v0;
            *(uint4*)(dst + 4) = v1;
        }

        // ---- PV: 2-pass (Phi*Vhi + Plo*Vhi), V hi only (V == K tiles) ----
        #pragma unroll
        for (int dt = 0; dt < 4; ++dt) {
            const uint32_t dcol = 2 * (pv_dbase + dt * 16);
            #pragma unroll
            for (int kk = 0; kk < 2; ++kk) {
                const uint32_t srow = pv_srow0 + kk * 16;
                uint32_t av = sb + kb + srow * 128 + (dcol ^ ((uint32_t)tr << 4));
                uint32_t vh[4];
                LDM4T(vh, av);
                uint32_t aH[4] = {PH[2*kk][0], PH[2*kk][1], PH[2*kk+1][0], PH[2*kk+1][1]};
                uint32_t aL[4] = {PL[2*kk][0], PL[2*kk][1], PL[2*kk+1][0], PL[2*kk+1][1]};
                MMA(Dacc[2 * dt],     aH, vh[0], vh[1]);
                MMA(Dacc[2 * dt + 1], aH, vh[2], vh[3]);
                MMA(Dacc[2 * dt],     aL, vh[0], vh[1]);
                MMA(Dacc[2 * dt + 1], aL, vh[2], vh[3]);
            }
        }

        if (c == 7) {
            // ---- head end: Z reduce (4 s-quarters per row) ----
            z0 += __shfl_xor_sync(0xffffffffu, z0, 1);
            z0 += __shfl_xor_sync(0xffffffffu, z0, 2);
            z1 += __shfl_xor_sync(0xffffffffu, z1, 1);
            z1 += __shfl_xor_sync(0xffffffffu, z1, 2);
            if ((lane & 3) == 0) {
                ZS[(qw * 16 + (lane >> 2)) * 4 + sw]     = z0;
                ZS[(qw * 16 + (lane >> 2) + 8) * 4 + sw] = z1;
            }
            __syncthreads();   // [F] Z in; tile reads + ESM reads done
            if (tid < 64) {
                float v = 1.0f / (ZS[4 * tid] + ZS[4 * tid + 1]
                                + ZS[4 * tid + 2] + ZS[4 * tid + 3]);
                ZI[tid] = v;
                g_invZ[(h * 128 + cta) * 64 + tid] = v;
            }

            // sw=1,2,3 publish D partials (pair1 + ESM free; prefetch -> pair0)
            if (sw != 0) {
                float* P = (sw == 1) ? P1 : (sw == 2) ? P2 : P3;
                #pragma unroll
                for (int nt = 0; nt < 8; ++nt) {
                    int col = nt * 8 + tig2;
                    *(float2*)(P + qw * 1024 + (lane >> 2) * 64 + col) =
                        make_float2(Dacc[nt][0], Dacc[nt][1]);
                    *(float2*)(P + qw * 1024 + ((lane >> 2) + 8) * 64 + col) =
                        make_float2(Dacc[nt][2], Dacc[nt][3]);
                }
            }
            __syncthreads();   // [G]

            if (sw == 0) {     // reduce 4 partials + normalize + store O
                const float iza = ZI[qw * 16 + (lane >> 2)];
                const float izb = ZI[qw * 16 + (lane >> 2) + 8];
                float* orow0 = out + ((size_t)(n * L_S + q0 + qw * 16 + (lane >> 2))) * DM + h * D;
                float* orow1 = orow0 + (size_t)8 * DM;
                #pragma unroll
                for (int nt = 0; nt < 8; ++nt) {
                    int col = nt * 8 + tig2;
                    int o0 = qw * 1024 + (lane >> 2) * 64 + col;
                    int o1 = qw * 1024 + ((lane >> 2) + 8) * 64 + col;
                    float2 a1 = *(float2*)(P1 + o0), b1 = *(float2*)(P1 + o1);
                    float2 a2 = *(float2*)(P2 + o0), b2 = *(float2*)(P2 + o1);
                    float2 a3 = *(float2*)(P3 + o0), b3 = *(float2*)(P3 + o1);
                    *(float2*)(orow0 + col) = make_float2(
                        (Dacc[nt][0] + a1.x + a2.x + a3.x) * iza,
                        (Dacc[nt][1] + a1.y + a2.y + a3.y) * iza);
                    *(float2*)(orow1 + col) = make_float2(
                        (Dacc[nt][2] + b1.x + b2.x + b3.x) * izb,
                        (Dacc[nt][3] + b1.y + b2.y + b3.y) * izb);
                }
            }
        }
    }
}

extern "C" void kernel_launch(void* const* d_in, const int* in_sizes, int n_in,
                              void* d_out, int out_size) {
    const float* in = (const float*)d_in[0];
    float* out = (float*)d_out;
    const size_t out_elems  = (size_t)N_B * L_S * DM;   // 8,388,608
    const size_t attn_elems = (size_t)N_B * L_S * L_S;  // 8,388,608
    int write_attn = (out_size >= (int)(out_elems + attn_elems)) ? 1 : 0;
    float* attn = out + out_elems;

    cudaFuncSetAttribute(attn_mma_kernel,
                         cudaFuncAttributeMaxDynamicSharedMemorySize, SMEM_SZ);

    prep_kernel<<<4096, 512>>>(in);                     // split to tile images
    dim3 grid(16, 8);                                   // 128 CTAs, 512 threads
    attn_mma_kernel<<<grid, THREADS, SMEM_SZ>>>(out);
    if (write_attn)
        merge_kernel<<<16384, 256>>>(attn);             // attn head-mean
}

// round 13
// speedup vs baseline: 6.3224x; 1.2347x over previous
#include <cuda_runtime.h>
#include <cuda_fp16.h>
#include <stdint.h>
#include <math.h>

#define N_B 8
#define L_S 1024
#define DM  1024
#define H   16
#define D   64
#define QB  64
#define CH  128
#define THREADS 512
// fold 1/sqrt(64) into exp: exp(0.125*S - m) = ex2(S*EXP_C - m2)
#define EXP_C 0.18033688011112042f
#define LOG2E 1.4426950408889634f

// SMEM byte offsets (hi-only tiles now)
#define SO_KH0 0          // pair0 hi (16KB)
#define SO_KH1 16384      // pair1 hi (16KB)
#define SO_QH  32768      // Q hi (8KB)
#define SO_ESM 40960      // e-stage: 64 rows x 272B (17408B); head-end: P2
#define SO_PR3 58368      // 16KB scratch for 3rd D-partial
#define SO_ZS  74752      // 64 x 4 f32 Z partials (1KB)
#define SO_ZI  75776      // 64 f32 invZ (256B)
#define SMEM_SZ 76032

// pre-split fp16 hi tile images (exact smem byte layout), 16KB per (n,h,c)
__device__ char     g_hi[(size_t)16 << 20];                  // 16MB
__device__ uint32_t g_p16[(size_t)16 * 128 * 64 * 512];      // 256MB fp16x2 e-planes
__device__ float    g_invZ[16 * 128 * 64];                   // 512KB

// ---------------- helpers ----------------
__device__ __forceinline__ uint32_t s2u(const void* p) {
    uint32_t a;
    asm("{ .reg .u64 t; cvta.to.shared.u64 t, %1; cvt.u32.u64 %0, t; }" : "=r"(a) : "l"(p));
    return a;
}
__device__ __forceinline__ uint32_t pack_f16(float lo, float hi) {    // lo -> bits[15:0]
    uint32_t r;
    asm("cvt.rn.f16x2.f32 %0, %1, %2;" : "=r"(r) : "f"(hi), "f"(lo));
    return r;
}
__device__ __forceinline__ float2 unpack_f16(uint32_t w) {
    __half2 h = *reinterpret_cast<__half2*>(&w);
    return __half22float2(h);
}
__device__ __forceinline__ float exps(float x, float m2) {   // exp(0.125*x) * 2^-m2
    float r, t = fmaf(x, EXP_C, -m2);
    asm("ex2.approx.ftz.f32 %0, %1;" : "=f"(r) : "f"(t));
    return r;
}

#define LDM4(r, ad) \
    asm volatile("ldmatrix.sync.aligned.m8n8.x4.shared.b16 {%0,%1,%2,%3}, [%4];" \
        : "=r"((r)[0]), "=r"((r)[1]), "=r"((r)[2]), "=r"((r)[3]) : "r"(ad))

#define LDM4T(r, ad) \
    asm volatile("ldmatrix.sync.aligned.m8n8.x4.trans.shared.b16 {%0,%1,%2,%3}, [%4];" \
        : "=r"((r)[0]), "=r"((r)[1]), "=r"((r)[2]), "=r"((r)[3]) : "r"(ad))

#define MMA(c, a, b0_, b1_) \
    asm volatile("mma.sync.aligned.m16n8k16.row.col.f32.f16.f16.f32 " \
        "{%0,%1,%2,%3}, {%4,%5,%6,%7}, {%8,%9}, {%0,%1,%2,%3};" \
        : "+f"((c)[0]), "+f"((c)[1]), "+f"((c)[2]), "+f"((c)[3]) \
        : "r"((a)[0]), "r"((a)[1]), "r"((a)[2]), "r"((a)[3]), "r"(b0_), "r"(b1_))

#define CPA16(sa, g) \
    asm volatile("cp.async.cg.shared.global [%0], [%1], 16;" :: "r"(sa), "l"(g))
#define CPA_COMMIT() asm volatile("cp.async.commit_group;" ::: "memory")
#define CPA_WAIT0()  asm volatile("cp.async.wait_group 0;" ::: "memory")
#define CPA_WAIT1()  asm volatile("cp.async.wait_group 1;" ::: "memory")

// ---------------- preprocess: f32 -> fp16 hi tile images ----------------
extern "C" __global__ void __launch_bounds__(512)
prep_kernel(const float* __restrict__ in)
{
    int idx = blockIdx.x * 512 + threadIdx.x;     // 2M threads, 1 float4 each
    int dqi = idx & 255;                          // h*16 + dq
    int s   = (idx >> 8) & 1023;
    int n   = idx >> 18;
    int dq = dqi & 15;
    float4 v = *(const float4*)(in + (((size_t)(n * 1024 + s)) << 10) + dqi * 4);
    uint32_t h0 = pack_f16(v.x, v.y);
    uint32_t h1 = pack_f16(v.z, v.w);
    uint32_t t = (uint32_t)((n * 16 + (dqi >> 4)) * 8 + (s >> 7));
    uint32_t b = (uint32_t)((s & 127) * 128 + ((dq * 8) ^ ((s & 7) << 4)));
    *(uint2*)(g_hi + (((size_t)t) << 14) + b) = make_uint2(h0, h1);
}

// ---------------- merge: attn = (1/16) sum_h e'_h * invZ'_h ----------------
extern "C" __global__ void __launch_bounds__(256)
merge_kernel(float* __restrict__ attn)
{
    int idx = blockIdx.x * 256 + threadIdx.x;     // 2.1M threads, 4 s each
    int s4 = idx & 255;                           // uint2 index (4 halfs)
    int qg = (idx >> 8) & 1023;
    int n  = idx >> 18;
    int cta = n * 16 + (qg >> 6);
    int ql  = qg & 63;
    float ax = 0.f, ay = 0.f, az = 0.f, aw = 0.f;
    #pragma unroll
    for (int h = 0; h < 16; ++h) {
        int base = (h * 128 + cta) * 64 + ql;
        uint2 w = *(const uint2*)(g_p16 + (((size_t)base) << 9) + s4 * 2);
        float iz = g_invZ[base];
        float2 v0 = unpack_f16(w.x), v1 = unpack_f16(w.y);
        ax += v0.x * iz; ay += v0.y * iz;
        az += v1.x * iz; aw += v1.y * iz;
    }
    ((float4*)attn)[idx] = make_float4(ax * (1.f / 16.f), ay * (1.f / 16.f),
                                       az * (1.f / 16.f), aw * (1.f / 16.f));
}

// ---------------- main attention kernel ----------------
extern "C" __global__ void __launch_bounds__(THREADS)
attn_mma_kernel(float* __restrict__ out)
{
    extern __shared__ __align__(1024) char smem[];
    const uint32_t sb = s2u(smem);
    float* ZS = (float*)(smem + SO_ZS);
    float* ZI = (float*)(smem + SO_ZI);
    float* P1 = (float*)(smem + SO_KH1);          // head-end D-partials
    float* P2 = (float*)(smem + SO_ESM);
    float* P3 = (float*)(smem + SO_PR3);

    const int tid  = threadIdx.x;
    const int lane = tid & 31;
    const int warp = tid >> 5;        // 16 warps
    const int qw   = warp & 3;        // q-tile group (16 rows)
    const int sw   = warp >> 2;       // s-quarter (32 cols)
    const int qb   = blockIdx.x, n = blockIdx.y;
    const int q0   = qb * QB;
    const int cta  = n * 16 + qb;

    const int qr   = qw * 16 + (lane >> 2);   // C/A-frag row (q)
    const int tig2 = 2 * (lane & 3);          // col pair base

    // trans-ldmatrix lane geometry for PV B-operand
    const int tg = lane >> 3, tr = lane & 7;
    const uint32_t pv_srow0 = (uint32_t)(sw * 32 + (tg & 1) * 8 + tr);
    const uint32_t pv_dbase = (uint32_t)((tg >> 1) * 8);

    // e-stage copy geometry: thread owns 32B of the logical 16KB chunk image
    const int cq  = tid >> 3;             // q row 0..63
    const int coff = (tid & 7) * 32;      // byte offset in 256B row

    // prologue: prefetch chunk (h=0,c=0) hi tile into pair0
    {
        const size_t tb = ((size_t)(n * 16 * 8)) << 14;     // tile (n,0,0)
        #pragma unroll
        for (int k = 0; k < 2; ++k) {
            uint32_t o = (uint32_t)(k * 512 + tid) * 16;
            CPA16(sb + SO_KH0 + o, g_hi + tb + o);
        }
        CPA_COMMIT();
    }

    uint32_t QHf[4][4];
    float Dacc[8][4];
    float z0 = 0.f, z1 = 0.f;
    float m2a = 0.f, m2b = 0.f;       // per-row exp shift (log2 units)
    size_t pbase = 0;

    for (int i = 0; i < H * 8; ++i) {
        const int h = i >> 3, c = i & 7;
        const uint32_t kb = (i & 1) ? SO_KH1 : SO_KH0;

        CPA_WAIT0();
        __syncthreads();   // [A] cur tile resident; ESM/P-buffers free

        if (c == 0) {
            // ---- Q hi tile image (8KB), own cp.async group ----
            const size_t tq = ((size_t)((n * 16 + h) * 8 + (qb >> 1))) << 14;
            const size_t qoff = (size_t)(qb & 1) * 8192;
            CPA16(sb + SO_QH + (uint32_t)tid * 16, g_hi + tq + qoff + tid * 16);
            CPA_COMMIT();
        }

        // ---- prefetch chunk i+1 into the other buffer ----
        if (i + 1 < H * 8) {
            const uint32_t dkb = ((i + 1) & 1) ? SO_KH1 : SO_KH0;
            const size_t tt = ((size_t)((n * 16 + ((i + 1) >> 3)) * 8 + ((i + 1) & 7))) << 14;
            #pragma unroll
            for (int k = 0; k < 2; ++k) {
                uint32_t o = (uint32_t)(k * 512 + tid) * 16;
                CPA16(sb + dkb + o, g_hi + tt + o);
            }
            CPA_COMMIT();
        }

        if (c == 0) {
            CPA_WAIT1();       // Q group (older) done; chunk prefetch may fly
            __syncthreads();
            // ---- persistent Q hi fragments ----
            const uint32_t row = qw * 16 + (lane & 15);
            const uint32_t swz = (row & 7) << 4;
            #pragma unroll
            for (int kk = 0; kk < 4; ++kk) {
                uint32_t col = kk * 32 + ((lane >> 4) << 4);
                LDM4(QHf[kk], sb + SO_QH + row * 128 + (col ^ swz));
            }
            // ---- per-row shift: m2 ~= 0.125*|q_row|^2 * log2(e) (hi parts) ----
            {
                float sa = 0.f, sbq = 0.f;
                const int r0 = qr, r1 = qr + 8;
                #pragma unroll
                for (int t = 0; t < 4; ++t) {
                    int dq = (lane & 3) * 4 + t;     // 8B group index 0..15
                    uint32_t b0 = r0 * 128 + ((dq * 8) ^ ((r0 & 7) << 4));
                    uint32_t b1 = r1 * 128 + ((dq * 8) ^ ((r1 & 7) << 4));
                    uint2 w0 = *(uint2*)(smem + SO_QH + b0);
                    uint2 w1 = *(uint2*)(smem + SO_QH + b1);
                    float2 a0 = unpack_f16(w0.x), a1 = unpack_f16(w0.y);
                    float2 c0 = unpack_f16(w1.x), c1 = unpack_f16(w1.y);
                    sa  += a0.x*a0.x + a0.y*a0.y + a1.x*a1.x + a1.y*a1.y;
                    sbq += c0.x*c0.x + c0.y*c0.y + c1.x*c1.x + c1.y*c1.y;
                }
                sa  += __shfl_xor_sync(0xffffffffu, sa, 1);
                sa  += __shfl_xor_sync(0xffffffffu, sa, 2);
                sbq += __shfl_xor_sync(0xffffffffu, sbq, 1);
                sbq += __shfl_xor_sync(0xffffffffu, sbq, 2);
                m2a = sa  * (0.125f * LOG2E);
                m2b = sbq * (0.125f * LOG2E);
            }
            #pragma unroll
            for (int x = 0; x < 8; ++x)
                #pragma unroll
                for (int j = 0; j < 4; ++j) Dacc[x][j] = 0.f;
            z0 = 0.f; z1 = 0.f;
            pbase = ((size_t)(h * 128 + cta)) << 15;
        }

        // ---- QK^T: single-pass fp16 (Qhi*Khi) ----
        float acc[4][4];
        #pragma unroll
        for (int x = 0; x < 4; ++x)
            #pragma unroll
            for (int j = 0; j < 4; ++j) acc[x][j] = 0.f;

        #pragma unroll
        for (int np = 0; np < 2; ++np) {
            const uint32_t rowb = sw * 32 + np * 16 + (lane & 7) + ((lane >> 4) << 3);
            const uint32_t rsw = (rowb & 7) << 4;
            #pragma unroll
            for (int kk = 0; kk < 4; ++kk) {
                uint32_t col = kk * 32 + ((lane >> 3) & 1) * 16;
                uint32_t bh[4];
                LDM4(bh, sb + kb + rowb * 128 + (col ^ rsw));
                MMA(acc[2 * np],     QHf[kk], bh[0], bh[1]);
                MMA(acc[2 * np + 1], QHf[kk], bh[2], bh[3]);
            }
        }

        // ---- shifted exp, Z accumulate, P pack, e' -> ESM ----
        uint32_t PH[4][2];
        #pragma unroll
        for (int nt = 0; nt < 4; ++nt) {
            float e0 = exps(acc[nt][0], m2a);
            float e1 = exps(acc[nt][1], m2a);
            float e2 = exps(acc[nt][2], m2b);
            float e3 = exps(acc[nt][3], m2b);
            z0 += e0 + e1; z1 += e2 + e3;
            uint32_t h0 = pack_f16(e0, e1);
            uint32_t h1 = pack_f16(e2, e3);
            PH[nt][0] = h0; PH[nt][1] = h1;
            uint32_t eb = sw * 64 + nt * 16 + (lane & 3) * 4;
            *(uint32_t*)(smem + SO_ESM + qr * 272 + eb)       = h0;
            *(uint32_t*)(smem + SO_ESM + (qr + 8) * 272 + eb) = h1;
        }
        __syncthreads();   // [E] ESM chunk image complete

        // ---- cooperative coalesced e-plane store (16KB -> g_p16) ----
        {
            const char* src = smem + SO_ESM + cq * 272 + coff;
            uint4 v0 = *(const uint4*)(src);
            uint4 v1 = *(const uint4*)(src + 16);
            uint32_t* dst = g_p16 + pbase + cq * 512 + c * 64 + (coff >> 2);
            *(uint4*)(dst)     = v0;
            *(uint4*)(dst + 4) = v1;
        }

        // ---- PV: single-pass fp16 (Phi*Vhi), V == K tiles ----
        #pragma unroll
        for (int dt = 0; dt < 4; ++dt) {
            const uint32_t dcol = 2 * (pv_dbase + dt * 16);
            #pragma unroll
            for (int kk = 0; kk < 2; ++kk) {
                const uint32_t srow = pv_srow0 + kk * 16;
                uint32_t vh[4];
                LDM4T(vh, sb + kb + srow * 128 + (dcol ^ ((uint32_t)tr << 4)));
                uint32_t aH[4] = {PH[2*kk][0], PH[2*kk][1], PH[2*kk+1][0], PH[2*kk+1][1]};
                MMA(Dacc[2 * dt],     aH, vh[0], vh[1]);
                MMA(Dacc[2 * dt + 1], aH, vh[2], vh[3]);
            }
        }

        if (c == 7) {
            // ---- head end: Z reduce (4 s-quarters per row) ----
            z0 += __shfl_xor_sync(0xffffffffu, z0, 1);
            z0 += __shfl_xor_sync(0xffffffffu, z0, 2);
            z1 += __shfl_xor_sync(0xffffffffu, z1, 1);
            z1 += __shfl_xor_sync(0xffffffffu, z1, 2);
            if ((lane & 3) == 0) {
                ZS[(qw * 16 + (lane >> 2)) * 4 + sw]     = z0;
                ZS[(qw * 16 + (lane >> 2) + 8) * 4 + sw] = z1;
            }
            __syncthreads();   // [F] Z in; tile reads + ESM reads done
            if (tid < 64) {
                float v = 1.0f / (ZS[4 * tid] + ZS[4 * tid + 1]
                                + ZS[4 * tid + 2] + ZS[4 * tid + 3]);
                ZI[tid] = v;
                g_invZ[(h * 128 + cta) * 64 + tid] = v;
            }

            // sw=1,2,3 publish D partials (KH1 + ESM free; prefetch -> KH0)
            if (sw != 0) {
                float* P = (sw == 1) ? P1 : (sw == 2) ? P2 : P3;
                #pragma unroll
                for (int nt = 0; nt < 8; ++nt) {
                    int col = nt * 8 + tig2;
                    *(float2*)(P + qw * 1024 + (lane >> 2) * 64 + col) =
                        make_float2(Dacc[nt][0], Dacc[nt][1]);
                    *(float2*)(P + qw * 1024 + ((lane >> 2) + 8) * 64 + col) =
                        make_float2(Dacc[nt][2], Dacc[nt][3]);
                }
            }
            __syncthreads();   // [G]

            if (sw == 0) {     // reduce 4 partials + normalize + store O
                const float iza = ZI[qw * 16 + (lane >> 2)];
                const float izb = ZI[qw * 16 + (lane >> 2) + 8];
                float* orow0 = out + ((size_t)(n * L_S + q0 + qw * 16 + (lane >> 2))) * DM + h * D;
                float* orow1 = orow0 + (size_t)8 * DM;
                #pragma unroll
                for (int nt = 0; nt < 8; ++nt) {
                    int col = nt * 8 + tig2;
                    int o0 = qw * 1024 + (lane >> 2) * 64 + col;
                    int o1 = qw * 1024 + ((lane >> 2) + 8) * 64 + col;
                    float2 a1 = *(float2*)(P1 + o0), b1 = *(float2*)(P1 + o1);
                    float2 a2 = *(float2*)(P2 + o0), b2 = *(float2*)(P2 + o1);
                    float2 a3 = *(float2*)(P3 + o0), b3 = *(float2*)(P3 + o1);
                    *(float2*)(orow0 + col) = make_float2(
                        (Dacc[nt][0] + a1.x + a2.x + a3.x) * iza,
                        (Dacc[nt][1] + a1.y + a2.y + a3.y) * iza);
                    *(float2*)(orow1 + col) = make_float2(
                        (Dacc[nt][2] + b1.x + b2.x + b3.x) * izb,
                        (Dacc[nt][3] + b1.y + b2.y + b3.y) * izb);
                }
            }
        }
    }
}

extern "C" void kernel_launch(void* const* d_in, const int* in_sizes, int n_in,
                              void* d_out, int out_size) {
    const float* in = (const float*)d_in[0];
    float* out = (float*)d_out;
    const size_t out_elems  = (size_t)N_B * L_S * DM;   // 8,388,608
    const size_t attn_elems = (size_t)N_B * L_S * L_S;  // 8,388,608
    int write_attn = (out_size >= (int)(out_elems + attn_elems)) ? 1 : 0;
    float* attn = out + out_elems;

    cudaFuncSetAttribute(attn_mma_kernel,
                         cudaFuncAttributeMaxDynamicSharedMemorySize, SMEM_SZ);

    prep_kernel<<<4096, 512>>>(in);                     // split to tile images
    dim3 grid(16, 8);                                   // 128 CTAs, 512 threads
    attn_mma_kernel<<<grid, THREADS, SMEM_SZ>>>(out);
    if (write_attn)
        merge_kernel<<<8192, 256>>>(attn);              // attn head-mean
}